// round 2
// baseline (speedup 1.0000x reference)
#include <cuda_runtime.h>
#include <cuda_bf16.h>
#include <math.h>

#define LSEQ 2048
#define DI   2048
#define DM   1024
#define E2   4096
#define NST  16
#define NBT  32

// ---------------- scratch ----------------
__device__ float g_xz[33554432];    // [4][4096][2048]  x rows 0..2047, z rows 2048..4095
__device__ float g_xc[16777216];    // [4][2048][2048]
__device__ float g_xdbl[786432];    // [4][96][2048]
__device__ float g_delta[16777216]; // [4][2048][2048]
__device__ float g_y[16777216];     // [4][2048][2048] (l,d)
__device__ float g_feat[65536];     // [32][2048]
__device__ float g_A[32768];        // [2048][16]

__device__ __forceinline__ float softplus_f(float x) {
    return fmaxf(x, 0.f) + log1pf(expf(-fabsf(x)));
}

__device__ __forceinline__ float blockReduceSum256(float v, float* red, int tid) {
    #pragma unroll
    for (int o = 16; o > 0; o >>= 1) v += __shfl_xor_sync(0xffffffffu, v, o);
    if ((tid & 31) == 0) red[tid >> 5] = v;
    __syncthreads();
    if (tid < 8) {
        float r = red[tid];
        #pragma unroll
        for (int o = 4; o > 0; o >>= 1) r += __shfl_xor_sync(0xffu, r, o);
        if (tid == 0) red[32] = r;
    }
    __syncthreads();
    float out = red[32];
    __syncthreads();
    return out;
}

__device__ __forceinline__ float blockReduceMax256(float v, float* red, int tid) {
    #pragma unroll
    for (int o = 16; o > 0; o >>= 1) v = fmaxf(v, __shfl_xor_sync(0xffffffffu, v, o));
    if ((tid & 31) == 0) red[tid >> 5] = v;
    __syncthreads();
    if (tid < 8) {
        float r = red[tid];
        #pragma unroll
        for (int o = 4; o > 0; o >>= 1) r = fmaxf(r, __shfl_xor_sync(0xffu, r, o));
        if (tid == 0) red[32] = r;
    }
    __syncthreads();
    float out = red[32];
    __syncthreads();
    return out;
}

// ---------------- SGEMM NT: C[M,N] = A(MxK) * B(NxK)^T ----------------
__global__ void __launch_bounds__(256) sgemm_nt(const float* __restrict__ Ag,
                                                const float* __restrict__ Bg,
                                                float* __restrict__ Cg,
                                                int M, int N, int K,
                                                long long sA, long long sB, long long sC) {
    const float* A = Ag + (long long)blockIdx.z * sA;
    const float* B = Bg + (long long)blockIdx.z * sB;
    float*       C = Cg + (long long)blockIdx.z * sC;
    int m0 = blockIdx.y * 128, n0 = blockIdx.x * 128;
    __shared__ float As[16][132];
    __shared__ float Bs[16][132];
    int tid = threadIdx.x;
    int tx = tid & 15, ty = tid >> 4;
    float acc[8][8];
    #pragma unroll
    for (int i = 0; i < 8; i++)
        #pragma unroll
        for (int j = 0; j < 8; j++) acc[i][j] = 0.f;

    for (int k0 = 0; k0 < K; k0 += 16) {
        #pragma unroll
        for (int r = 0; r < 2; r++) {
            int idx = tid + r * 256;
            int m = idx >> 2;
            int kq = (idx & 3) << 2;
            float4 v = make_float4(0.f, 0.f, 0.f, 0.f);
            if (m0 + m < M) v = *(const float4*)(A + (long long)(m0 + m) * K + k0 + kq);
            As[kq + 0][m] = v.x; As[kq + 1][m] = v.y; As[kq + 2][m] = v.z; As[kq + 3][m] = v.w;
        }
        #pragma unroll
        for (int r = 0; r < 2; r++) {
            int idx = tid + r * 256;
            int n = idx >> 2;
            int kq = (idx & 3) << 2;
            float4 v = *(const float4*)(B + (long long)(n0 + n) * K + k0 + kq);
            Bs[kq + 0][n] = v.x; Bs[kq + 1][n] = v.y; Bs[kq + 2][n] = v.z; Bs[kq + 3][n] = v.w;
        }
        __syncthreads();
        #pragma unroll
        for (int k = 0; k < 16; k++) {
            float4 a0 = *(const float4*)&As[k][ty * 8];
            float4 a1 = *(const float4*)&As[k][ty * 8 + 4];
            float4 b0 = *(const float4*)&Bs[k][tx * 8];
            float4 b1 = *(const float4*)&Bs[k][tx * 8 + 4];
            float ar[8] = {a0.x, a0.y, a0.z, a0.w, a1.x, a1.y, a1.z, a1.w};
            float br[8] = {b0.x, b0.y, b0.z, b0.w, b1.x, b1.y, b1.z, b1.w};
            #pragma unroll
            for (int i = 0; i < 8; i++)
                #pragma unroll
                for (int j = 0; j < 8; j++) acc[i][j] += ar[i] * br[j];
        }
        __syncthreads();
    }
    #pragma unroll
    for (int i = 0; i < 8; i++) {
        int m = m0 + ty * 8 + i;
        if (m >= M) continue;
        float* cp = C + (long long)m * N + n0 + tx * 8;
        *(float4*)cp       = make_float4(acc[i][0], acc[i][1], acc[i][2], acc[i][3]);
        *(float4*)(cp + 4) = make_float4(acc[i][4], acc[i][5], acc[i][6], acc[i][7]);
    }
}

// ---------------- SGEMM NN: C[M,N] = A(MxK) * B(KxN); optional softplus+bias ----------------
__global__ void __launch_bounds__(256) sgemm_nn(const float* __restrict__ Ag,
                                                const float* __restrict__ Bg,
                                                float* __restrict__ Cg,
                                                int M, int N, int K,
                                                long long sA, long long sB, long long sC,
                                                const float* __restrict__ bias, int epi) {
    const float* A = Ag + (long long)blockIdx.z * sA;
    const float* B = Bg + (long long)blockIdx.z * sB;
    float*       C = Cg + (long long)blockIdx.z * sC;
    int m0 = blockIdx.y * 128, n0 = blockIdx.x * 128;
    __shared__ float As[16][132];
    __shared__ float Bs[16][132];
    int tid = threadIdx.x;
    int tx = tid & 15, ty = tid >> 4;
    float acc[8][8];
    #pragma unroll
    for (int i = 0; i < 8; i++)
        #pragma unroll
        for (int j = 0; j < 8; j++) acc[i][j] = 0.f;

    for (int k0 = 0; k0 < K; k0 += 16) {
        #pragma unroll
        for (int r = 0; r < 2; r++) {
            int idx = tid + r * 256;
            int m = idx >> 2;
            int kq = (idx & 3) << 2;
            float4 v = make_float4(0.f, 0.f, 0.f, 0.f);
            if (m0 + m < M) v = *(const float4*)(A + (long long)(m0 + m) * K + k0 + kq);
            As[kq + 0][m] = v.x; As[kq + 1][m] = v.y; As[kq + 2][m] = v.z; As[kq + 3][m] = v.w;
        }
        #pragma unroll
        for (int r = 0; r < 2; r++) {
            int idx = tid + r * 256;
            int k = idx >> 5;
            int nq = (idx & 31) << 2;
            *(float4*)&Bs[k][nq] = *(const float4*)(B + (long long)(k0 + k) * N + n0 + nq);
        }
        __syncthreads();
        #pragma unroll
        for (int k = 0; k < 16; k++) {
            float4 a0 = *(const float4*)&As[k][ty * 8];
            float4 a1 = *(const float4*)&As[k][ty * 8 + 4];
            float4 b0 = *(const float4*)&Bs[k][tx * 8];
            float4 b1 = *(const float4*)&Bs[k][tx * 8 + 4];
            float ar[8] = {a0.x, a0.y, a0.z, a0.w, a1.x, a1.y, a1.z, a1.w};
            float br[8] = {b0.x, b0.y, b0.z, b0.w, b1.x, b1.y, b1.z, b1.w};
            #pragma unroll
            for (int i = 0; i < 8; i++)
                #pragma unroll
                for (int j = 0; j < 8; j++) acc[i][j] += ar[i] * br[j];
        }
        __syncthreads();
    }
    #pragma unroll
    for (int i = 0; i < 8; i++) {
        int m = m0 + ty * 8 + i;
        if (m >= M) continue;
        if (epi == 1) {
            float bv = bias[m];
            #pragma unroll
            for (int j = 0; j < 8; j++) acc[i][j] = softplus_f(acc[i][j] + bv);
        }
        float* cp = C + (long long)m * N + n0 + tx * 8;
        *(float4*)cp       = make_float4(acc[i][0], acc[i][1], acc[i][2], acc[i][3]);
        *(float4*)(cp + 4) = make_float4(acc[i][4], acc[i][5], acc[i][6], acc[i][7]);
    }
}

// ---------------- FFT channel-alignment features ----------------
// 32 threads, 32 channels per block; grid (64 chan groups, 32 bt)
__global__ void __launch_bounds__(32) fft_feat_kernel(const float* __restrict__ xz,
                                                      float* __restrict__ feat) {
    __shared__ float sx[256 * 33];
    __shared__ float twc[16], tws[16];
    int tid = threadIdx.x;
    int bt = blockIdx.y;
    int b = bt >> 3, t = bt & 7;
    int c0 = blockIdx.x * 32;
    if (tid < 16) {
        float ang = tid * 0.39269908169872414f; // 2*pi/16
        twc[tid] = cosf(ang);
        tws[tid] = sinf(ang);
    }
    const float* xb = xz + ((long long)(b * E2 + c0)) * LSEQ + t * 256;
    for (int i = tid; i < 32 * 256; i += 32) {
        int c = i >> 8, l = i & 255;
        sx[l * 33 + c] = xb[(long long)c * LSEQ + l];
    }
    __syncwarp();
    int c = tid;
    float S_tot = 0.f, S_high = 0.f;
    for (int wq = 0; wq < 9; wq++) {
        float Rr[16], Ri[16];
        #pragma unroll
        for (int h = 0; h < 16; h++) {
            float rr = 0.f, ri = 0.f;
            #pragma unroll
            for (int w = 0; w < 16; w++) {
                float v = sx[(h * 16 + w) * 33 + c];
                int id = (w * wq) & 15;
                rr += v * twc[id];
                ri -= v * tws[id];
            }
            Rr[h] = rr; Ri[h] = ri;
        }
        #pragma unroll
        for (int hq = 0; hq < 16; hq++) {
            float fre = 0.f, fim = 0.f;
            #pragma unroll
            for (int h = 0; h < 16; h++) {
                int id = (h * hq) & 15;
                float cc = twc[id], sn = tws[id];
                fre += Rr[h] * cc + Ri[h] * sn;
                fim += Ri[h] * cc - Rr[h] * sn;
            }
            float mag = sqrtf(fre * fre + fim * fim + 1e-8f);
            S_tot += mag;
            int hs = (hq + 8) & 15;
            int ws = wq + 4; if (ws >= 9) ws -= 9;
            float dh = (hs - 8) * (1.0f / 16.0f);
            float dw = (ws - 4) * (1.0f / 9.0f);
            if (dh * dh + dw * dw >= 0.25f) S_high += mag;
        }
    }
    feat[(long long)bt * DI + c0 + c] = S_high / (S_tot + 1e-8f);
}

// ---------------- alignment loss ----------------
__global__ void __launch_bounds__(256) loss_kernel(const float* __restrict__ feat,
                                                   float* __restrict__ out, long long loss_idx) {
    __shared__ float g[DI];
    __shared__ float red[40];
    int tid = threadIdx.x;
    for (int cc = tid; cc < DI; cc += 256) g[cc] = 0.f;
    __syncthreads();
    for (int i = 0; i < NBT; i++) {
        float ss = 0.f;
        for (int cc = tid; cc < DI; cc += 256) {
            float v = feat[i * DI + cc];
            ss += v * v;
        }
        ss = blockReduceSum256(ss, red, tid);
        float inv = 1.f / fmaxf(sqrtf(ss), 1e-12f);
        for (int cc = tid; cc < DI; cc += 256) g[cc] += feat[i * DI + cc] * inv;
        __syncthreads();
    }
    float tt = 0.f;
    for (int cc = tid; cc < DI; cc += 256) tt += g[cc] * g[cc];
    tt = blockReduceSum256(tt, red, tid);
    if (tid == 0) out[loss_idx] = 1.f - tt / (float)(NBT * NBT);
}

// ---------------- A preparation (invert_A) ----------------
__global__ void __launch_bounds__(256) aprep_kernel(const float* __restrict__ feat,
                                                    const float* __restrict__ A_log,
                                                    float* __restrict__ Aout) {
    __shared__ float sf[DI];
    __shared__ float satt[DI];
    __shared__ float red[40];
    __shared__ float wmx[8][16], wmn[8][16];
    __shared__ float colMx[16], colMn[16];
    int tid = threadIdx.x;
    int lane = tid & 31, wid = tid >> 5;
    // mean over bt
    for (int cc = tid; cc < DI; cc += 256) {
        float s = 0.f;
        for (int i = 0; i < NBT; i++) s += feat[i * DI + cc];
        sf[cc] = s * (1.0f / NBT);
    }
    __syncthreads();
    float mx = -3.4e38f;
    for (int cc = tid; cc < DI; cc += 256) mx = fmaxf(mx, sf[cc]);
    mx = blockReduceMax256(mx, red, tid);
    float se = 0.f;
    for (int cc = tid; cc < DI; cc += 256) {
        float e = expf(sf[cc] - mx);
        sf[cc] = e;
        se += e;
    }
    se = blockReduceSum256(se, red, tid);
    float inv_se = 1.f / se;
    // attention + col max/min
    float cm[16], cn[16];
    #pragma unroll
    for (int n = 0; n < 16; n++) { cm[n] = -3.4e38f; cn[n] = 3.4e38f; }
    float am = 0.f;
    for (int d = tid; d < DI; d += 256) {
        float ss = 0.f;
        #pragma unroll
        for (int n = 0; n < 16; n++) {
            float al = A_log[d * 16 + n];
            float e = expf(al);
            ss += e * e;
            cm[n] = fmaxf(cm[n], al);
            cn[n] = fminf(cn[n], al);
        }
        float an = sqrtf(ss);
        satt[d] = an;
        am = fmaxf(am, an);
    }
    am = blockReduceMax256(am, red, tid);
    #pragma unroll
    for (int o = 16; o > 0; o >>= 1) {
        #pragma unroll
        for (int n = 0; n < 16; n++) {
            cm[n] = fmaxf(cm[n], __shfl_xor_sync(0xffffffffu, cm[n], o));
            cn[n] = fminf(cn[n], __shfl_xor_sync(0xffffffffu, cn[n], o));
        }
    }
    if (lane == 0) {
        #pragma unroll
        for (int n = 0; n < 16; n++) { wmx[wid][n] = cm[n]; wmn[wid][n] = cn[n]; }
    }
    __syncthreads();
    if (tid < 16) {
        float m = -3.4e38f, mn = 3.4e38f;
        for (int w = 0; w < 8; w++) { m = fmaxf(m, wmx[w][tid]); mn = fminf(mn, wmn[w][tid]); }
        colMx[tid] = m; colMn[tid] = mn;
    }
    __syncthreads();
    float inv_am = 1.f / (am + 1e-8f);
    for (int i = tid; i < DI * 16; i += 256) {
        int d = i >> 4, n = i & 15;
        float f = sf[d] * inv_se;
        float att = satt[d] * inv_am;
        float alpha = fminf(fmaxf(f * (1.f - att), 0.f), 1.f);
        float al = A_log[i];
        float fl = colMx[n] + colMn[n] - al;
        float an = (1.f - alpha) * al + alpha * fl;
        Aout[i] = -expf(an);
    }
}

// ---------------- causal depthwise conv (width 4) + silu ----------------
__global__ void __launch_bounds__(256) conv_kernel(const float* __restrict__ xz,
                                                   const float* __restrict__ cw,
                                                   const float* __restrict__ cb,
                                                   float* __restrict__ xc) {
    __shared__ float row[LSEQ + 3];
    int rid = blockIdx.x;            // b*DI + d
    int b = rid >> 11, d = rid & 2047;
    int tid = threadIdx.x;
    const float* xp = xz + ((long long)b * E2 + d) * LSEQ;
    if (tid < 3) row[tid] = 0.f;
    for (int i = tid; i < LSEQ; i += 256) row[3 + i] = xp[i];
    __syncthreads();
    float w0 = cw[d * 4 + 0], w1 = cw[d * 4 + 1], w2 = cw[d * 4 + 2], w3 = cw[d * 4 + 3];
    float bb = cb[d];
    float* op = xc + ((long long)b * DI + d) * LSEQ;
    for (int i = tid; i < LSEQ; i += 256) {
        float v = bb + w0 * row[i] + w1 * row[i + 1] + w2 * row[i + 2] + w3 * row[i + 3];
        op[i] = v / (1.f + expf(-v));
    }
}

// ---------------- selective scan ----------------
// block: 256 = 16 chains x 16 state lanes; grid (DI/16, B)
__global__ void __launch_bounds__(256) scan_kernel(const float* __restrict__ delta,
                                                   const float* __restrict__ xc,
                                                   const float* __restrict__ xz,
                                                   const float* __restrict__ xdbl,
                                                   const float* __restrict__ A,
                                                   const float* __restrict__ Dp,
                                                   float* __restrict__ y) {
    __shared__ float sDel[64][17], sU[64][17], sZ[64][17];
    __shared__ float sB[64][17], sC[64][17], sY[64][17];
    int tid = threadIdx.x;
    int ci = tid >> 4, n = tid & 15;
    int b = blockIdx.y;
    int d0 = blockIdx.x * 16;
    int d = d0 + ci;
    const float* delp = delta + ((long long)b * DI + d0) * LSEQ;
    const float* up   = xc    + ((long long)b * DI + d0) * LSEQ;
    const float* zp   = xz    + ((long long)b * E2 + DI + d0) * LSEQ;
    const float* bp   = xdbl  + ((long long)b * 96 + 64) * LSEQ;
    const float* cp   = xdbl  + ((long long)b * 96 + 80) * LSEQ;
    float*       yp   = y     + (long long)b * LSEQ * DI;
    float a = A[d * 16 + n];
    float dD = Dp[d];
    float s = 0.f;
    for (int l0 = 0; l0 < LSEQ; l0 += 64) {
        for (int i = tid; i < 1024; i += 256) {
            int cc = i >> 6, j = i & 63;
            sDel[j][cc] = delp[(long long)cc * LSEQ + l0 + j];
            sU[j][cc]   = up[(long long)cc * LSEQ + l0 + j];
            sZ[j][cc]   = zp[(long long)cc * LSEQ + l0 + j];
            sB[j][cc]   = bp[(long long)cc * LSEQ + l0 + j];
            sC[j][cc]   = cp[(long long)cc * LSEQ + l0 + j];
        }
        __syncthreads();
        #pragma unroll 4
        for (int j = 0; j < 64; j++) {
            float dl = sDel[j][ci];
            float u  = sU[j][ci];
            float bb = sB[j][n];
            float ccv = sC[j][n];
            s = s * __expf(dl * a) + (dl * u) * bb;
            float p = s * ccv;
            #pragma unroll
            for (int o = 8; o > 0; o >>= 1) p += __shfl_xor_sync(0xffffffffu, p, o, 16);
            if (n == 0) {
                float z = sZ[j][ci];
                float yy = (p + u * dD) * (z / (1.f + __expf(-z)));
                sY[j][ci] = yy;
            }
        }
        __syncthreads();
        for (int i = tid; i < 1024; i += 256) {
            int j = i >> 4, cc = i & 15;
            yp[(long long)(l0 + j) * DI + d0 + cc] = sY[j][cc];
        }
        __syncthreads();
    }
}

// ---------------- launch ----------------
extern "C" void kernel_launch(void* const* d_in, const int* in_sizes, int n_in,
                              void* d_out, int out_size) {
    const float* hidden    = (const float*)d_in[0];
    const float* in_proj_w = (const float*)d_in[4];
    const float* conv_w    = (const float*)d_in[5];
    const float* conv_b    = (const float*)d_in[6];
    const float* x_proj_w  = (const float*)d_in[7];
    const float* dt_proj_w = (const float*)d_in[8];
    const float* dt_proj_b = (const float*)d_in[9];
    const float* A_log     = (const float*)d_in[10];
    const float* Dparam    = (const float*)d_in[11];
    const float* out_proj_w= (const float*)d_in[12];
    float* out = (float*)d_out;

    float *xzp, *xcp, *xdblp, *deltap, *yp, *featp, *Ap;
    cudaGetSymbolAddress((void**)&xzp, g_xz);
    cudaGetSymbolAddress((void**)&xcp, g_xc);
    cudaGetSymbolAddress((void**)&xdblp, g_xdbl);
    cudaGetSymbolAddress((void**)&deltap, g_delta);
    cudaGetSymbolAddress((void**)&yp, g_y);
    cudaGetSymbolAddress((void**)&featp, g_feat);
    cudaGetSymbolAddress((void**)&Ap, g_A);

    // 1) xz = in_proj: per b, C[4096,2048] = W(4096x1024) * hidden[b](2048x1024)^T
    {
        dim3 grid(LSEQ / 128, E2 / 128, 4);
        sgemm_nt<<<grid, 256>>>(in_proj_w, hidden, xzp, E2, LSEQ, DM,
                                0LL, (long long)LSEQ * DM, (long long)E2 * LSEQ);
    }
    // 2) FFT features
    {
        dim3 grid(DI / 32, 32);
        fft_feat_kernel<<<grid, 32>>>(xzp, featp);
    }
    // 3) loss -> out[last]
    loss_kernel<<<1, 256>>>(featp, out, (long long)out_size - 1);
    // 4) A prep
    aprep_kernel<<<1, 256>>>(featp, A_log, Ap);
    // 5) conv + silu
    conv_kernel<<<4 * DI, 256>>>(xzp, conv_w, conv_b, xcp);
    // 6) x_dbl: per b, C[96,2048] = x_proj_w(96x2048) * xc[b](2048x2048)
    {
        dim3 grid(LSEQ / 128, 1, 4);
        sgemm_nn<<<grid, 256>>>(x_proj_w, xcp, xdblp, 96, LSEQ, DI,
                                0LL, (long long)DI * LSEQ, (long long)96 * LSEQ,
                                (const float*)0, 0);
    }
    // 7) delta: per b, C[2048,2048] = dt_proj_w(2048x64) * dt_low(64x2048), softplus+bias
    {
        dim3 grid(LSEQ / 128, DI / 128, 4);
        sgemm_nn<<<grid, 256>>>(dt_proj_w, xdblp, deltap, DI, LSEQ, 64,
                                0LL, (long long)96 * LSEQ, (long long)DI * LSEQ,
                                dt_proj_b, 1);
    }
    // 8) scan -> y (l,d)
    {
        dim3 grid(DI / 16, 4);
        scan_kernel<<<grid, 256>>>(deltap, xcp, xzp, xdblp, Ap, Dparam, yp);
    }
    // 9) out = y @ out_proj^T: per b, C[2048,1024] = y[b](2048x2048) * W(1024x2048)^T
    {
        dim3 grid(DM / 128, LSEQ / 128, 4);
        sgemm_nt<<<grid, 256>>>(yp, out_proj_w, out, LSEQ, DM, DI,
                                (long long)LSEQ * DI, 0LL, (long long)LSEQ * DM);
    }
}

// round 4
// speedup vs baseline: 1.3399x; 1.3399x over previous
#include <cuda_runtime.h>
#include <cuda_bf16.h>
#include <math.h>
#include <stdint.h>

#define LSEQ 2048
#define DI   2048
#define DM   1024
#define E2   4096
#define NST  16
#define NBT  32

// ---------------- scratch ----------------
__device__ float g_xz[33554432];    // [4][4096][2048]
__device__ float g_xc[16777216];    // [4][2048][2048]
__device__ float g_xdbl[786432];    // [4][96][2048]
__device__ float g_delta[16777216]; // [4][2048][2048]
__device__ float g_y[16777216];     // [4][2048][2048] (l,d)
__device__ float g_feat[65536];     // [32][2048]
__device__ float g_A[32768];        // [2048][16]

__device__ __forceinline__ float softplus_f(float x) {
    return fmaxf(x, 0.f) + log1pf(expf(-fabsf(x)));
}

__device__ __forceinline__ uint32_t f2tf(float f) {
    uint32_t r;
    asm("cvt.rna.tf32.f32 %0, %1;" : "=r"(r) : "f"(f));
    return r;
}

__device__ __forceinline__ void mma_tf32(float c[4], const uint32_t a[4], const uint32_t b[2]) {
    asm volatile(
        "mma.sync.aligned.m16n8k8.row.col.f32.tf32.tf32.f32 "
        "{%0,%1,%2,%3}, {%4,%5,%6,%7}, {%8,%9}, {%0,%1,%2,%3};\n"
        : "+f"(c[0]), "+f"(c[1]), "+f"(c[2]), "+f"(c[3])
        : "r"(a[0]), "r"(a[1]), "r"(a[2]), "r"(a[3]), "r"(b[0]), "r"(b[1]));
}

__device__ __forceinline__ float blockReduceSum256(float v, float* red, int tid) {
    #pragma unroll
    for (int o = 16; o > 0; o >>= 1) v += __shfl_xor_sync(0xffffffffu, v, o);
    if ((tid & 31) == 0) red[tid >> 5] = v;
    __syncthreads();
    if (tid < 8) {
        float r = red[tid];
        #pragma unroll
        for (int o = 4; o > 0; o >>= 1) r += __shfl_xor_sync(0xffu, r, o);
        if (tid == 0) red[32] = r;
    }
    __syncthreads();
    float out = red[32];
    __syncthreads();
    return out;
}

__device__ __forceinline__ float blockReduceMax256(float v, float* red, int tid) {
    #pragma unroll
    for (int o = 16; o > 0; o >>= 1) v = fmaxf(v, __shfl_xor_sync(0xffffffffu, v, o));
    if ((tid & 31) == 0) red[tid >> 5] = v;
    __syncthreads();
    if (tid < 8) {
        float r = red[tid];
        #pragma unroll
        for (int o = 4; o > 0; o >>= 1) r = fmaxf(r, __shfl_xor_sync(0xffu, r, o));
        if (tid == 0) red[32] = r;
    }
    __syncthreads();
    float out = red[32];
    __syncthreads();
    return out;
}

// =====================================================================
// TF32 tensor-core GEMM, block tile 128x128x32, 8 warps (2x4), warp 64x32
// TRANSB=1: C[M,N] = A(MxK) * B(NxK)^T   (both k-inner row-major)
// TRANSB=0: C[M,N] = A(MxK) * B(KxN)     (ldb = N)
// EPI=1: C = softplus(C + bias[m])
// =====================================================================
template<int TRANSB, int EPI>
__global__ void __launch_bounds__(256) tc_gemm(const float* __restrict__ Ag,
                                               const float* __restrict__ Bg,
                                               float* __restrict__ Cg,
                                               int M, int N, int K,
                                               long long sA, long long sB, long long sC,
                                               const float* __restrict__ bias) {
    const float* A = Ag + (long long)blockIdx.z * sA;
    const float* B = Bg + (long long)blockIdx.z * sB;
    float*       C = Cg + (long long)blockIdx.z * sC;
    const int m0 = blockIdx.y * 128, n0 = blockIdx.x * 128;

    __shared__ uint32_t As[32 * 136];
    __shared__ uint32_t Bs[32 * 136];

    const int tid = threadIdx.x;
    const int wid = tid >> 5, lane = tid & 31;
    const int wm = (wid >> 2) * 64;      // warp m offset (0 / 64)
    const int wn = (wid & 3) * 32;       // warp n offset (0/32/64/96)
    const int g = lane >> 2, tg = lane & 3;

    float c[4][4][4];
    #pragma unroll
    for (int mi = 0; mi < 4; mi++)
        #pragma unroll
        for (int ni = 0; ni < 4; ni++)
            #pragma unroll
            for (int r = 0; r < 4; r++) c[mi][ni][r] = 0.f;

    for (int k0 = 0; k0 < K; k0 += 32) {
        // load A tile 128x32 -> As[k][m]
        #pragma unroll
        for (int r = 0; r < 4; r++) {
            int idx = tid + r * 256;        // 1024 float4 loads
            int m = idx >> 3;
            int kq = (idx & 7) << 2;
            float4 v = make_float4(0.f, 0.f, 0.f, 0.f);
            if (m0 + m < M) v = *(const float4*)(A + (long long)(m0 + m) * K + k0 + kq);
            As[(kq + 0) * 136 + m] = f2tf(v.x);
            As[(kq + 1) * 136 + m] = f2tf(v.y);
            As[(kq + 2) * 136 + m] = f2tf(v.z);
            As[(kq + 3) * 136 + m] = f2tf(v.w);
        }
        // load B tile -> Bs[k][n]
        if (TRANSB) {
            #pragma unroll
            for (int r = 0; r < 4; r++) {
                int idx = tid + r * 256;
                int n = idx >> 3;
                int kq = (idx & 7) << 2;
                float4 v = *(const float4*)(B + (long long)(n0 + n) * K + k0 + kq);
                Bs[(kq + 0) * 136 + n] = f2tf(v.x);
                Bs[(kq + 1) * 136 + n] = f2tf(v.y);
                Bs[(kq + 2) * 136 + n] = f2tf(v.z);
                Bs[(kq + 3) * 136 + n] = f2tf(v.w);
            }
        } else {
            #pragma unroll
            for (int r = 0; r < 4; r++) {
                int idx = tid + r * 256;
                int k = idx >> 5;
                int nq = (idx & 31) << 2;
                float4 v = *(const float4*)(B + (long long)(k0 + k) * N + n0 + nq);
                Bs[k * 136 + nq + 0] = f2tf(v.x);
                Bs[k * 136 + nq + 1] = f2tf(v.y);
                Bs[k * 136 + nq + 2] = f2tf(v.z);
                Bs[k * 136 + nq + 3] = f2tf(v.w);
            }
        }
        __syncthreads();

        #pragma unroll
        for (int kk = 0; kk < 32; kk += 8) {
            uint32_t a[4][4], bfr[4][2];
            const uint32_t* Ar0 = &As[(kk + tg) * 136];
            const uint32_t* Ar1 = &As[(kk + tg + 4) * 136];
            #pragma unroll
            for (int mi = 0; mi < 4; mi++) {
                int mr = wm + mi * 16 + g;
                a[mi][0] = Ar0[mr];
                a[mi][1] = Ar0[mr + 8];
                a[mi][2] = Ar1[mr];
                a[mi][3] = Ar1[mr + 8];
            }
            const uint32_t* Br0 = &Bs[(kk + tg) * 136];
            const uint32_t* Br1 = &Bs[(kk + tg + 4) * 136];
            #pragma unroll
            for (int ni = 0; ni < 4; ni++) {
                int nc = wn + ni * 8 + g;
                bfr[ni][0] = Br0[nc];
                bfr[ni][1] = Br1[nc];
            }
            #pragma unroll
            for (int mi = 0; mi < 4; mi++)
                #pragma unroll
                for (int ni = 0; ni < 4; ni++)
                    mma_tf32(c[mi][ni], a[mi], bfr[ni]);
        }
        __syncthreads();
    }

    // epilogue
    #pragma unroll
    for (int mi = 0; mi < 4; mi++) {
        int r0 = m0 + wm + mi * 16 + g;
        int r1 = r0 + 8;
        float b0v = 0.f, b1v = 0.f;
        if (EPI) {
            if (r0 < M) b0v = bias[r0];
            if (r1 < M) b1v = bias[r1];
        }
        #pragma unroll
        for (int ni = 0; ni < 4; ni++) {
            int col = n0 + wn + ni * 8 + 2 * tg;
            float v0 = c[mi][ni][0], v1 = c[mi][ni][1];
            float v2 = c[mi][ni][2], v3 = c[mi][ni][3];
            if (EPI) {
                v0 = softplus_f(v0 + b0v); v1 = softplus_f(v1 + b0v);
                v2 = softplus_f(v2 + b1v); v3 = softplus_f(v3 + b1v);
            }
            if (r0 < M) *(float2*)(C + (long long)r0 * N + col) = make_float2(v0, v1);
            if (r1 < M) *(float2*)(C + (long long)r1 * N + col) = make_float2(v2, v3);
        }
    }
}

// ---------------- FFT channel-alignment features ----------------
__global__ void __launch_bounds__(32) fft_feat_kernel(const float* __restrict__ xz,
                                                      float* __restrict__ feat) {
    __shared__ float sx[256 * 33];
    __shared__ float twc[16], tws[16];
    int tid = threadIdx.x;
    int bt = blockIdx.y;
    int b = bt >> 3, t = bt & 7;
    int c0 = blockIdx.x * 32;
    if (tid < 16) {
        float ang = tid * 0.39269908169872414f;
        twc[tid] = cosf(ang);
        tws[tid] = sinf(ang);
    }
    const float* xb = xz + ((long long)(b * E2 + c0)) * LSEQ + t * 256;
    for (int i = tid; i < 32 * 256; i += 32) {
        int c = i >> 8, l = i & 255;
        sx[l * 33 + c] = xb[(long long)c * LSEQ + l];
    }
    __syncwarp();
    int c = tid;
    float S_tot = 0.f, S_high = 0.f;
    for (int wq = 0; wq < 9; wq++) {
        float Rr[16], Ri[16];
        #pragma unroll
        for (int h = 0; h < 16; h++) {
            float rr = 0.f, ri = 0.f;
            #pragma unroll
            for (int w = 0; w < 16; w++) {
                float v = sx[(h * 16 + w) * 33 + c];
                int id = (w * wq) & 15;
                rr += v * twc[id];
                ri -= v * tws[id];
            }
            Rr[h] = rr; Ri[h] = ri;
        }
        #pragma unroll
        for (int hq = 0; hq < 16; hq++) {
            float fre = 0.f, fim = 0.f;
            #pragma unroll
            for (int h = 0; h < 16; h++) {
                int id = (h * hq) & 15;
                float cc = twc[id], sn = tws[id];
                fre += Rr[h] * cc + Ri[h] * sn;
                fim += Ri[h] * cc - Rr[h] * sn;
            }
            float mag = sqrtf(fre * fre + fim * fim + 1e-8f);
            S_tot += mag;
            int hs = (hq + 8) & 15;
            int ws = wq + 4; if (ws >= 9) ws -= 9;
            float dh = (hs - 8) * (1.0f / 16.0f);
            float dw = (ws - 4) * (1.0f / 9.0f);
            if (dh * dh + dw * dw >= 0.25f) S_high += mag;
        }
    }
    feat[(long long)bt * DI + c0 + c] = S_high / (S_tot + 1e-8f);
}

// ---------------- alignment loss ----------------
__global__ void __launch_bounds__(256) loss_kernel(const float* __restrict__ feat,
                                                   float* __restrict__ out, long long loss_idx) {
    __shared__ float g[DI];
    __shared__ float red[40];
    int tid = threadIdx.x;
    for (int cc = tid; cc < DI; cc += 256) g[cc] = 0.f;
    __syncthreads();
    for (int i = 0; i < NBT; i++) {
        float ss = 0.f;
        for (int cc = tid; cc < DI; cc += 256) {
            float v = feat[i * DI + cc];
            ss += v * v;
        }
        ss = blockReduceSum256(ss, red, tid);
        float inv = 1.f / fmaxf(sqrtf(ss), 1e-12f);
        for (int cc = tid; cc < DI; cc += 256) g[cc] += feat[i * DI + cc] * inv;
        __syncthreads();
    }
    float tt = 0.f;
    for (int cc = tid; cc < DI; cc += 256) tt += g[cc] * g[cc];
    tt = blockReduceSum256(tt, red, tid);
    if (tid == 0) out[loss_idx] = 1.f - tt / (float)(NBT * NBT);
}

// ---------------- A preparation (invert_A) ----------------
__global__ void __launch_bounds__(256) aprep_kernel(const float* __restrict__ feat,
                                                    const float* __restrict__ A_log,
                                                    float* __restrict__ Aout) {
    __shared__ float sf[DI];
    __shared__ float satt[DI];
    __shared__ float red[40];
    __shared__ float wmx[8][16], wmn[8][16];
    __shared__ float colMx[16], colMn[16];
    int tid = threadIdx.x;
    int lane = tid & 31, wid = tid >> 5;
    for (int cc = tid; cc < DI; cc += 256) {
        float s = 0.f;
        for (int i = 0; i < NBT; i++) s += feat[i * DI + cc];
        sf[cc] = s * (1.0f / NBT);
    }
    __syncthreads();
    float mx = -3.4e38f;
    for (int cc = tid; cc < DI; cc += 256) mx = fmaxf(mx, sf[cc]);
    mx = blockReduceMax256(mx, red, tid);
    float se = 0.f;
    for (int cc = tid; cc < DI; cc += 256) {
        float e = expf(sf[cc] - mx);
        sf[cc] = e;
        se += e;
    }
    se = blockReduceSum256(se, red, tid);
    float inv_se = 1.f / se;
    float cm[16], cn[16];
    #pragma unroll
    for (int n = 0; n < 16; n++) { cm[n] = -3.4e38f; cn[n] = 3.4e38f; }
    float am = 0.f;
    for (int d = tid; d < DI; d += 256) {
        float ss = 0.f;
        #pragma unroll
        for (int n = 0; n < 16; n++) {
            float al = A_log[d * 16 + n];
            float e = expf(al);
            ss += e * e;
            cm[n] = fmaxf(cm[n], al);
            cn[n] = fminf(cn[n], al);
        }
        float an = sqrtf(ss);
        satt[d] = an;
        am = fmaxf(am, an);
    }
    am = blockReduceMax256(am, red, tid);
    #pragma unroll
    for (int o = 16; o > 0; o >>= 1) {
        #pragma unroll
        for (int n = 0; n < 16; n++) {
            cm[n] = fmaxf(cm[n], __shfl_xor_sync(0xffffffffu, cm[n], o));
            cn[n] = fminf(cn[n], __shfl_xor_sync(0xffffffffu, cn[n], o));
        }
    }
    if (lane == 0) {
        #pragma unroll
        for (int n = 0; n < 16; n++) { wmx[wid][n] = cm[n]; wmn[wid][n] = cn[n]; }
    }
    __syncthreads();
    if (tid < 16) {
        float m = -3.4e38f, mn = 3.4e38f;
        for (int w = 0; w < 8; w++) { m = fmaxf(m, wmx[w][tid]); mn = fminf(mn, wmn[w][tid]); }
        colMx[tid] = m; colMn[tid] = mn;
    }
    __syncthreads();
    float inv_am = 1.f / (am + 1e-8f);
    for (int i = tid; i < DI * 16; i += 256) {
        int d = i >> 4, n = i & 15;
        float f = sf[d] * inv_se;
        float att = satt[d] * inv_am;
        float alpha = fminf(fmaxf(f * (1.f - att), 0.f), 1.f);
        float al = A_log[i];
        float fl = colMx[n] + colMn[n] - al;
        float an = (1.f - alpha) * al + alpha * fl;
        Aout[i] = -expf(an);
    }
}

// ---------------- causal depthwise conv (width 4) + silu ----------------
__global__ void __launch_bounds__(256) conv_kernel(const float* __restrict__ xz,
                                                   const float* __restrict__ cw,
                                                   const float* __restrict__ cb,
                                                   float* __restrict__ xc) {
    __shared__ float row[LSEQ + 3];
    int rid = blockIdx.x;
    int b = rid >> 11, d = rid & 2047;
    int tid = threadIdx.x;
    const float* xp = xz + ((long long)b * E2 + d) * LSEQ;
    if (tid < 3) row[tid] = 0.f;
    for (int i = tid; i < LSEQ; i += 256) row[3 + i] = xp[i];
    __syncthreads();
    float w0 = cw[d * 4 + 0], w1 = cw[d * 4 + 1], w2 = cw[d * 4 + 2], w3 = cw[d * 4 + 3];
    float bb = cb[d];
    float* op = xc + ((long long)b * DI + d) * LSEQ;
    for (int i = tid; i < LSEQ; i += 256) {
        float v = bb + w0 * row[i] + w1 * row[i + 1] + w2 * row[i + 2] + w3 * row[i + 3];
        op[i] = v / (1.f + expf(-v));
    }
}

// ---------------- selective scan ----------------
__global__ void __launch_bounds__(256) scan_kernel(const float* __restrict__ delta,
                                                   const float* __restrict__ xc,
                                                   const float* __restrict__ xz,
                                                   const float* __restrict__ xdbl,
                                                   const float* __restrict__ A,
                                                   const float* __restrict__ Dp,
                                                   float* __restrict__ y) {
    __shared__ float sDel[64][17], sU[64][17], sZ[64][17];
    __shared__ float sB[64][17], sC[64][17], sY[64][17];
    int tid = threadIdx.x;
    int ci = tid >> 4, n = tid & 15;
    int b = blockIdx.y;
    int d0 = blockIdx.x * 16;
    int d = d0 + ci;
    const float* delp = delta + ((long long)b * DI + d0) * LSEQ;
    const float* up   = xc    + ((long long)b * DI + d0) * LSEQ;
    const float* zp   = xz    + ((long long)b * E2 + DI + d0) * LSEQ;
    const float* bp   = xdbl  + ((long long)b * 96 + 64) * LSEQ;
    const float* cp   = xdbl  + ((long long)b * 96 + 80) * LSEQ;
    float*       yp   = y     + (long long)b * LSEQ * DI;
    float a = A[d * 16 + n];
    float dD = Dp[d];
    float s = 0.f;
    for (int l0 = 0; l0 < LSEQ; l0 += 64) {
        for (int i = tid; i < 1024; i += 256) {
            int cc = i >> 6, j = i & 63;
            sDel[j][cc] = delp[(long long)cc * LSEQ + l0 + j];
            sU[j][cc]   = up[(long long)cc * LSEQ + l0 + j];
            sZ[j][cc]   = zp[(long long)cc * LSEQ + l0 + j];
            sB[j][cc]   = bp[(long long)cc * LSEQ + l0 + j];
            sC[j][cc]   = cp[(long long)cc * LSEQ + l0 + j];
        }
        __syncthreads();
        #pragma unroll 4
        for (int j = 0; j < 64; j++) {
            float dl = sDel[j][ci];
            float u  = sU[j][ci];
            float bb = sB[j][n];
            float ccv = sC[j][n];
            s = s * __expf(dl * a) + (dl * u) * bb;
            float p = s * ccv;
            #pragma unroll
            for (int o = 8; o > 0; o >>= 1) p += __shfl_xor_sync(0xffffffffu, p, o, 16);
            if (n == 0) {
                float z = sZ[j][ci];
                float yy = (p + u * dD) * (z / (1.f + __expf(-z)));
                sY[j][ci] = yy;
            }
        }
        __syncthreads();
        for (int i = tid; i < 1024; i += 256) {
            int j = i >> 4, cc = i & 15;
            yp[(long long)(l0 + j) * DI + d0 + cc] = sY[j][cc];
        }
        __syncthreads();
    }
}

// ---------------- launch ----------------
extern "C" void kernel_launch(void* const* d_in, const int* in_sizes, int n_in,
                              void* d_out, int out_size) {
    const float* hidden    = (const float*)d_in[0];
    const float* in_proj_w = (const float*)d_in[4];
    const float* conv_w    = (const float*)d_in[5];
    const float* conv_b    = (const float*)d_in[6];
    const float* x_proj_w  = (const float*)d_in[7];
    const float* dt_proj_w = (const float*)d_in[8];
    const float* dt_proj_b = (const float*)d_in[9];
    const float* A_log     = (const float*)d_in[10];
    const float* Dparam    = (const float*)d_in[11];
    const float* out_proj_w= (const float*)d_in[12];
    float* out = (float*)d_out;

    float *xzp, *xcp, *xdblp, *deltap, *yp, *featp, *Ap;
    cudaGetSymbolAddress((void**)&xzp, g_xz);
    cudaGetSymbolAddress((void**)&xcp, g_xc);
    cudaGetSymbolAddress((void**)&xdblp, g_xdbl);
    cudaGetSymbolAddress((void**)&deltap, g_delta);
    cudaGetSymbolAddress((void**)&yp, g_y);
    cudaGetSymbolAddress((void**)&featp, g_feat);
    cudaGetSymbolAddress((void**)&Ap, g_A);

    // 1) xz = in_proj
    {
        dim3 grid(LSEQ / 128, E2 / 128, 4);
        tc_gemm<1, 0><<<grid, 256>>>(in_proj_w, hidden, xzp, E2, LSEQ, DM,
                                     0LL, (long long)LSEQ * DM, (long long)E2 * LSEQ,
                                     (const float*)0);
    }
    // 2) FFT features
    {
        dim3 grid(DI / 32, 32);
        fft_feat_kernel<<<grid, 32>>>(xzp, featp);
    }
    // 3) loss -> out[last]
    loss_kernel<<<1, 256>>>(featp, out, (long long)out_size - 1);
    // 4) A prep
    aprep_kernel<<<1, 256>>>(featp, A_log, Ap);
    // 5) conv + silu
    conv_kernel<<<4 * DI, 256>>>(xzp, conv_w, conv_b, xcp);
    // 6) x_dbl
    {
        dim3 grid(LSEQ / 128, 1, 4);
        tc_gemm<0, 0><<<grid, 256>>>(x_proj_w, xcp, xdblp, 96, LSEQ, DI,
                                     0LL, (long long)DI * LSEQ, (long long)96 * LSEQ,
                                     (const float*)0);
    }
    // 7) delta (softplus + bias epilogue)
    {
        dim3 grid(LSEQ / 128, DI / 128, 4);
        tc_gemm<0, 1><<<grid, 256>>>(dt_proj_w, xdblp, deltap, DI, LSEQ, 64,
                                     0LL, (long long)96 * LSEQ, (long long)DI * LSEQ,
                                     dt_proj_b);
    }
    // 8) scan -> y (l,d)
    {
        dim3 grid(DI / 16, 4);
        scan_kernel<<<grid, 256>>>(deltap, xcp, xzp, xdblp, Ap, Dparam, yp);
    }
    // 9) out = y @ out_proj^T
    {
        dim3 grid(DM / 128, LSEQ / 128, 4);
        tc_gemm<1, 0><<<grid, 256>>>(yp, out_proj_w, out, LSEQ, DM, DI,
                                     (long long)LSEQ * DI, 0LL, (long long)LSEQ * DM,
                                     (const float*)0);
    }
}

// round 5
// speedup vs baseline: 1.9358x; 1.4448x over previous
#include <cuda_runtime.h>
#include <cuda_bf16.h>
#include <math.h>
#include <stdint.h>

#define LSEQ 2048
#define DI   2048
#define DM   1024
#define E2   4096
#define NST  16
#define NBT  32

// ---------------- scratch ----------------
__device__ float g_xz[33554432];    // [4][4096][2048]
__device__ float g_xc[16777216];    // [4][2048][2048]
__device__ float g_xdbl[786432];    // [4][96][2048]
__device__ float g_delta[16777216]; // [4][2048][2048]
__device__ float g_y[16777216];     // [4][2048][2048] (l,d)
__device__ float g_feat[65536];     // [32][2048]
__device__ float g_A[32768];        // [2048][16]

__device__ __forceinline__ float softplus_f(float x) {
    return fmaxf(x, 0.f) + log1pf(expf(-fabsf(x)));
}

__device__ __forceinline__ uint32_t f2tf(float f) {
    uint32_t r;
    asm("cvt.rna.tf32.f32 %0, %1;" : "=r"(r) : "f"(f));
    return r;
}

__device__ __forceinline__ void mma_tf32(float c[4], const uint32_t a[4], const uint32_t b[2]) {
    asm volatile(
        "mma.sync.aligned.m16n8k8.row.col.f32.tf32.tf32.f32 "
        "{%0,%1,%2,%3}, {%4,%5,%6,%7}, {%8,%9}, {%0,%1,%2,%3};\n"
        : "+f"(c[0]), "+f"(c[1]), "+f"(c[2]), "+f"(c[3])
        : "r"(a[0]), "r"(a[1]), "r"(a[2]), "r"(a[3]), "r"(b[0]), "r"(b[1]));
}

__device__ __forceinline__ void cp_async16(uint32_t smem_addr, const void* gptr) {
    asm volatile("cp.async.cg.shared.global [%0], [%1], 16;\n" :: "r"(smem_addr), "l"(gptr));
}
__device__ __forceinline__ void cp_commit() {
    asm volatile("cp.async.commit_group;\n");
}
template<int N>
__device__ __forceinline__ void cp_wait() {
    asm volatile("cp.async.wait_group %0;\n" :: "n"(N));
}

__device__ __forceinline__ float blockReduceSum256(float v, float* red, int tid) {
    #pragma unroll
    for (int o = 16; o > 0; o >>= 1) v += __shfl_xor_sync(0xffffffffu, v, o);
    if ((tid & 31) == 0) red[tid >> 5] = v;
    __syncthreads();
    if (tid < 8) {
        float r = red[tid];
        #pragma unroll
        for (int o = 4; o > 0; o >>= 1) r += __shfl_xor_sync(0xffu, r, o);
        if (tid == 0) red[32] = r;
    }
    __syncthreads();
    float out = red[32];
    __syncthreads();
    return out;
}

__device__ __forceinline__ float blockReduceMax256(float v, float* red, int tid) {
    #pragma unroll
    for (int o = 16; o > 0; o >>= 1) v = fmaxf(v, __shfl_xor_sync(0xffffffffu, v, o));
    if ((tid & 31) == 0) red[tid >> 5] = v;
    __syncthreads();
    if (tid < 8) {
        float r = red[tid];
        #pragma unroll
        for (int o = 4; o > 0; o >>= 1) r = fmaxf(r, __shfl_xor_sync(0xffu, r, o));
        if (tid == 0) red[32] = r;
    }
    __syncthreads();
    float out = red[32];
    __syncthreads();
    return out;
}

// =====================================================================
// Pipelined TF32 GEMM: block 128x128x32, 3-stage cp.async, 8 warps (2x4)
// TRANSB=1: C[M,N] = A(MxK) * B(NxK)^T
// TRANSB=0: C[M,N] = A(MxK) * B(KxN), ldb=N
// EPI=1: softplus(C + bias[m])
// Smem: A[128][36] raw fp32 per stage; B: TRANSB -> [128][36], NN -> [32][136]
// =====================================================================
#define APITCH 36
#define BPITCH_NN 136
#define ASZ (128 * APITCH)             // floats per A stage
#define BSZ_T (128 * APITCH)
#define BSZ_N (32 * BPITCH_NN)
#define STAGES 3

template<int TRANSB, int EPI>
__global__ void __launch_bounds__(256) tc_gemm(const float* __restrict__ Ag,
                                               const float* __restrict__ Bg,
                                               float* __restrict__ Cg,
                                               int M, int N, int K,
                                               long long sA, long long sB, long long sC,
                                               const float* __restrict__ bias) {
    extern __shared__ float smem[];
    const int BSZ = TRANSB ? BSZ_T : BSZ_N;
    float* AsBase = smem;                       // STAGES * ASZ
    float* BsBase = smem + STAGES * ASZ;        // STAGES * BSZ

    const float* A = Ag + (long long)blockIdx.z * sA;
    const float* B = Bg + (long long)blockIdx.z * sB;
    float*       C = Cg + (long long)blockIdx.z * sC;
    const int m0 = blockIdx.y * 128, n0 = blockIdx.x * 128;

    const int tid = threadIdx.x;
    const int wid = tid >> 5, lane = tid & 31;
    const int wm = (wid >> 2) * 64;
    const int wn = (wid & 3) * 32;
    const int g = lane >> 2, tg = lane & 3;

    const int nk = K >> 5;

    // cp.async issue for one k-tile into stage s (guarded by kt < nk)
    auto issue_tile = [&](int s, int kt) {
        if (kt < nk) {
            int k0 = kt << 5;
            float* As = AsBase + s * ASZ;
            float* Bs = BsBase + s * BSZ;
            // A: 128 rows x 32 floats = 1024 x 16B chunks, 4 per thread
            #pragma unroll
            for (int r = 0; r < 4; r++) {
                int c = tid + r * 256;
                int row = c >> 3;
                int kq = (c & 7) << 2;
                int mrow = m0 + row;
                if (mrow >= M) mrow = M - 1;   // clamp: rows >= M discarded at epilogue
                uint32_t dst = (uint32_t)__cvta_generic_to_shared(As + row * APITCH + kq);
                cp_async16(dst, A + (long long)mrow * K + k0 + kq);
            }
            if (TRANSB) {
                #pragma unroll
                for (int r = 0; r < 4; r++) {
                    int c = tid + r * 256;
                    int row = c >> 3;
                    int kq = (c & 7) << 2;
                    uint32_t dst = (uint32_t)__cvta_generic_to_shared(Bs + row * APITCH + kq);
                    cp_async16(dst, B + (long long)(n0 + row) * K + k0 + kq);
                }
            } else {
                #pragma unroll
                for (int r = 0; r < 4; r++) {
                    int c = tid + r * 256;
                    int k = c >> 5;
                    int nq = (c & 31) << 2;
                    uint32_t dst = (uint32_t)__cvta_generic_to_shared(Bs + k * BPITCH_NN + nq);
                    cp_async16(dst, B + (long long)(k0 + k) * N + n0 + nq);
                }
            }
        }
        cp_commit();   // always commit (possibly empty) to keep group ledger exact
    };

    float c[4][4][4];
    #pragma unroll
    for (int mi = 0; mi < 4; mi++)
        #pragma unroll
        for (int ni = 0; ni < 4; ni++)
            #pragma unroll
            for (int r = 0; r < 4; r++) c[mi][ni][r] = 0.f;

    // prologue: stages 0..STAGES-2
    issue_tile(0, 0);
    issue_tile(1, 1);

    for (int kt = 0; kt < nk; kt++) {
        issue_tile((kt + 2) % STAGES, kt + 2);
        cp_wait<2>();
        __syncthreads();
        const float* As = AsBase + (kt % STAGES) * ASZ;
        const float* Bs = BsBase + (kt % STAGES) * BSZ;

        #pragma unroll
        for (int kk = 0; kk < 32; kk += 8) {
            uint32_t a[4][4], bfr[4][2];
            #pragma unroll
            for (int mi = 0; mi < 4; mi++) {
                const float* Ar = As + (wm + mi * 16 + g) * APITCH + kk + tg;
                a[mi][0] = f2tf(Ar[0]);
                a[mi][1] = f2tf(Ar[8 * APITCH]);
                a[mi][2] = f2tf(Ar[4]);
                a[mi][3] = f2tf(Ar[8 * APITCH + 4]);
            }
            if (TRANSB) {
                #pragma unroll
                for (int ni = 0; ni < 4; ni++) {
                    const float* Br = Bs + (wn + ni * 8 + g) * APITCH + kk + tg;
                    bfr[ni][0] = f2tf(Br[0]);
                    bfr[ni][1] = f2tf(Br[4]);
                }
            } else {
                #pragma unroll
                for (int ni = 0; ni < 4; ni++) {
                    const float* Br = Bs + (kk + tg) * BPITCH_NN + wn + ni * 8 + g;
                    bfr[ni][0] = f2tf(Br[0]);
                    bfr[ni][1] = f2tf(Br[4 * BPITCH_NN]);
                }
            }
            #pragma unroll
            for (int mi = 0; mi < 4; mi++)
                #pragma unroll
                for (int ni = 0; ni < 4; ni++)
                    mma_tf32(c[mi][ni], a[mi], bfr[ni]);
        }
        __syncthreads();   // all reads of stage kt%STAGES done before it is rewritten
    }

    // epilogue (a-fragment rows: r0 = base+g, r1 = base+g+8; cols 2*tg, 2*tg+1)
    #pragma unroll
    for (int mi = 0; mi < 4; mi++) {
        int r0 = m0 + wm + mi * 16 + g;
        int r1 = r0 + 8;
        float b0v = 0.f, b1v = 0.f;
        if (EPI) {
            if (r0 < M) b0v = bias[r0];
            if (r1 < M) b1v = bias[r1];
        }
        #pragma unroll
        for (int ni = 0; ni < 4; ni++) {
            int col = n0 + wn + ni * 8 + 2 * tg;
            float v0 = c[mi][ni][0], v1 = c[mi][ni][1];
            float v2 = c[mi][ni][2], v3 = c[mi][ni][3];
            if (EPI) {
                v0 = softplus_f(v0 + b0v); v1 = softplus_f(v1 + b0v);
                v2 = softplus_f(v2 + b1v); v3 = softplus_f(v3 + b1v);
            }
            if (r0 < M) *(float2*)(C + (long long)r0 * N + col) = make_float2(v0, v1);
            if (r1 < M) *(float2*)(C + (long long)r1 * N + col) = make_float2(v2, v3);
        }
    }
}

#define SMEM_T ((STAGES * (ASZ + BSZ_T)) * 4)
#define SMEM_N ((STAGES * (ASZ + BSZ_N)) * 4)

// ---------------- FFT channel-alignment features ----------------
__global__ void __launch_bounds__(32) fft_feat_kernel(const float* __restrict__ xz,
                                                      float* __restrict__ feat) {
    __shared__ float sx[256 * 33];
    __shared__ float twc[16], tws[16];
    int tid = threadIdx.x;
    int bt = blockIdx.y;
    int b = bt >> 3, t = bt & 7;
    int c0 = blockIdx.x * 32;
    if (tid < 16) {
        float ang = tid * 0.39269908169872414f;
        twc[tid] = cosf(ang);
        tws[tid] = sinf(ang);
    }
    const float* xb = xz + ((long long)(b * E2 + c0)) * LSEQ + t * 256;
    for (int i = tid; i < 32 * 256; i += 32) {
        int c = i >> 8, l = i & 255;
        sx[l * 33 + c] = xb[(long long)c * LSEQ + l];
    }
    __syncwarp();
    int c = tid;
    float S_tot = 0.f, S_high = 0.f;
    for (int wq = 0; wq < 9; wq++) {
        float Rr[16], Ri[16];
        #pragma unroll
        for (int h = 0; h < 16; h++) {
            float rr = 0.f, ri = 0.f;
            #pragma unroll
            for (int w = 0; w < 16; w++) {
                float v = sx[(h * 16 + w) * 33 + c];
                int id = (w * wq) & 15;
                rr += v * twc[id];
                ri -= v * tws[id];
            }
            Rr[h] = rr; Ri[h] = ri;
        }
        #pragma unroll
        for (int hq = 0; hq < 16; hq++) {
            float fre = 0.f, fim = 0.f;
            #pragma unroll
            for (int h = 0; h < 16; h++) {
                int id = (h * hq) & 15;
                float cc = twc[id], sn = tws[id];
                fre += Rr[h] * cc + Ri[h] * sn;
                fim += Ri[h] * cc - Rr[h] * sn;
            }
            float mag = sqrtf(fre * fre + fim * fim + 1e-8f);
            S_tot += mag;
            int hs = (hq + 8) & 15;
            int ws = wq + 4; if (ws >= 9) ws -= 9;
            float dh = (hs - 8) * (1.0f / 16.0f);
            float dw = (ws - 4) * (1.0f / 9.0f);
            if (dh * dh + dw * dw >= 0.25f) S_high += mag;
        }
    }
    feat[(long long)bt * DI + c0 + c] = S_high / (S_tot + 1e-8f);
}

// ---------------- alignment loss ----------------
__global__ void __launch_bounds__(256) loss_kernel(const float* __restrict__ feat,
                                                   float* __restrict__ out, long long loss_idx) {
    __shared__ float g[DI];
    __shared__ float red[40];
    int tid = threadIdx.x;
    for (int cc = tid; cc < DI; cc += 256) g[cc] = 0.f;
    __syncthreads();
    for (int i = 0; i < NBT; i++) {
        float ss = 0.f;
        for (int cc = tid; cc < DI; cc += 256) {
            float v = feat[i * DI + cc];
            ss += v * v;
        }
        ss = blockReduceSum256(ss, red, tid);
        float inv = 1.f / fmaxf(sqrtf(ss), 1e-12f);
        for (int cc = tid; cc < DI; cc += 256) g[cc] += feat[i * DI + cc] * inv;
        __syncthreads();
    }
    float tt = 0.f;
    for (int cc = tid; cc < DI; cc += 256) tt += g[cc] * g[cc];
    tt = blockReduceSum256(tt, red, tid);
    if (tid == 0) out[loss_idx] = 1.f - tt / (float)(NBT * NBT);
}

// ---------------- A preparation (invert_A) ----------------
__global__ void __launch_bounds__(256) aprep_kernel(const float* __restrict__ feat,
                                                    const float* __restrict__ A_log,
                                                    float* __restrict__ Aout) {
    __shared__ float sf[DI];
    __shared__ float satt[DI];
    __shared__ float red[40];
    __shared__ float wmx[8][16], wmn[8][16];
    __shared__ float colMx[16], colMn[16];
    int tid = threadIdx.x;
    int lane = tid & 31, wid = tid >> 5;
    for (int cc = tid; cc < DI; cc += 256) {
        float s = 0.f;
        for (int i = 0; i < NBT; i++) s += feat[i * DI + cc];
        sf[cc] = s * (1.0f / NBT);
    }
    __syncthreads();
    float mx = -3.4e38f;
    for (int cc = tid; cc < DI; cc += 256) mx = fmaxf(mx, sf[cc]);
    mx = blockReduceMax256(mx, red, tid);
    float se = 0.f;
    for (int cc = tid; cc < DI; cc += 256) {
        float e = expf(sf[cc] - mx);
        sf[cc] = e;
        se += e;
    }
    se = blockReduceSum256(se, red, tid);
    float inv_se = 1.f / se;
    float cm[16], cn[16];
    #pragma unroll
    for (int n = 0; n < 16; n++) { cm[n] = -3.4e38f; cn[n] = 3.4e38f; }
    float am = 0.f;
    for (int d = tid; d < DI; d += 256) {
        float ss = 0.f;
        #pragma unroll
        for (int n = 0; n < 16; n++) {
            float al = A_log[d * 16 + n];
            float e = expf(al);
            ss += e * e;
            cm[n] = fmaxf(cm[n], al);
            cn[n] = fminf(cn[n], al);
        }
        float an = sqrtf(ss);
        satt[d] = an;
        am = fmaxf(am, an);
    }
    am = blockReduceMax256(am, red, tid);
    #pragma unroll
    for (int o = 16; o > 0; o >>= 1) {
        #pragma unroll
        for (int n = 0; n < 16; n++) {
            cm[n] = fmaxf(cm[n], __shfl_xor_sync(0xffffffffu, cm[n], o));
            cn[n] = fminf(cn[n], __shfl_xor_sync(0xffffffffu, cn[n], o));
        }
    }
    if (lane == 0) {
        #pragma unroll
        for (int n = 0; n < 16; n++) { wmx[wid][n] = cm[n]; wmn[wid][n] = cn[n]; }
    }
    __syncthreads();
    if (tid < 16) {
        float m = -3.4e38f, mn = 3.4e38f;
        for (int w = 0; w < 8; w++) { m = fmaxf(m, wmx[w][tid]); mn = fminf(mn, wmn[w][tid]); }
        colMx[tid] = m; colMn[tid] = mn;
    }
    __syncthreads();
    float inv_am = 1.f / (am + 1e-8f);
    for (int i = tid; i < DI * 16; i += 256) {
        int d = i >> 4, n = i & 15;
        float f = sf[d] * inv_se;
        float att = satt[d] * inv_am;
        float alpha = fminf(fmaxf(f * (1.f - att), 0.f), 1.f);
        float al = A_log[i];
        float fl = colMx[n] + colMn[n] - al;
        float an = (1.f - alpha) * al + alpha * fl;
        Aout[i] = -expf(an);
    }
}

// ---------------- causal depthwise conv (width 4) + silu ----------------
__global__ void __launch_bounds__(256) conv_kernel(const float* __restrict__ xz,
                                                   const float* __restrict__ cw,
                                                   const float* __restrict__ cb,
                                                   float* __restrict__ xc) {
    __shared__ float row[LSEQ + 3];
    int rid = blockIdx.x;
    int b = rid >> 11, d = rid & 2047;
    int tid = threadIdx.x;
    const float* xp = xz + ((long long)b * E2 + d) * LSEQ;
    if (tid < 3) row[tid] = 0.f;
    for (int i = tid; i < LSEQ; i += 256) row[3 + i] = xp[i];
    __syncthreads();
    float w0 = cw[d * 4 + 0], w1 = cw[d * 4 + 1], w2 = cw[d * 4 + 2], w3 = cw[d * 4 + 3];
    float bb = cb[d];
    float* op = xc + ((long long)b * DI + d) * LSEQ;
    for (int i = tid; i < LSEQ; i += 256) {
        float v = bb + w0 * row[i] + w1 * row[i + 1] + w2 * row[i + 2] + w3 * row[i + 3];
        op[i] = v / (1.f + expf(-v));
    }
}

// ---------------- selective scan ----------------
__global__ void __launch_bounds__(256) scan_kernel(const float* __restrict__ delta,
                                                   const float* __restrict__ xc,
                                                   const float* __restrict__ xz,
                                                   const float* __restrict__ xdbl,
                                                   const float* __restrict__ A,
                                                   const float* __restrict__ Dp,
                                                   float* __restrict__ y) {
    __shared__ float sDel[64][17], sU[64][17], sZ[64][17];
    __shared__ float sB[64][17], sC[64][17], sY[64][17];
    int tid = threadIdx.x;
    int ci = tid >> 4, n = tid & 15;
    int b = blockIdx.y;
    int d0 = blockIdx.x * 16;
    int d = d0 + ci;
    const float* delp = delta + ((long long)b * DI + d0) * LSEQ;
    const float* up   = xc    + ((long long)b * DI + d0) * LSEQ;
    const float* zp   = xz    + ((long long)b * E2 + DI + d0) * LSEQ;
    const float* bp   = xdbl  + ((long long)b * 96 + 64) * LSEQ;
    const float* cp   = xdbl  + ((long long)b * 96 + 80) * LSEQ;
    float*       yp   = y     + (long long)b * LSEQ * DI;
    float a = A[d * 16 + n];
    float dD = Dp[d];
    float s = 0.f;
    for (int l0 = 0; l0 < LSEQ; l0 += 64) {
        for (int i = tid; i < 1024; i += 256) {
            int cc = i >> 6, j = i & 63;
            sDel[j][cc] = delp[(long long)cc * LSEQ + l0 + j];
            sU[j][cc]   = up[(long long)cc * LSEQ + l0 + j];
            sZ[j][cc]   = zp[(long long)cc * LSEQ + l0 + j];
            sB[j][cc]   = bp[(long long)cc * LSEQ + l0 + j];
            sC[j][cc]   = cp[(long long)cc * LSEQ + l0 + j];
        }
        __syncthreads();
        #pragma unroll 4
        for (int j = 0; j < 64; j++) {
            float dl = sDel[j][ci];
            float u  = sU[j][ci];
            float bb = sB[j][n];
            float ccv = sC[j][n];
            s = s * __expf(dl * a) + (dl * u) * bb;
            float p = s * ccv;
            #pragma unroll
            for (int o = 8; o > 0; o >>= 1) p += __shfl_xor_sync(0xffffffffu, p, o, 16);
            if (n == 0) {
                float z = sZ[j][ci];
                float yy = (p + u * dD) * (z / (1.f + __expf(-z)));
                sY[j][ci] = yy;
            }
        }
        __syncthreads();
        for (int i = tid; i < 1024; i += 256) {
            int j = i >> 4, cc = i & 15;
            yp[(long long)(l0 + j) * DI + d0 + cc] = sY[j][cc];
        }
        __syncthreads();
    }
}

// ---------------- launch ----------------
extern "C" void kernel_launch(void* const* d_in, const int* in_sizes, int n_in,
                              void* d_out, int out_size) {
    const float* hidden    = (const float*)d_in[0];
    const float* in_proj_w = (const float*)d_in[4];
    const float* conv_w    = (const float*)d_in[5];
    const float* conv_b    = (const float*)d_in[6];
    const float* x_proj_w  = (const float*)d_in[7];
    const float* dt_proj_w = (const float*)d_in[8];
    const float* dt_proj_b = (const float*)d_in[9];
    const float* A_log     = (const float*)d_in[10];
    const float* Dparam    = (const float*)d_in[11];
    const float* out_proj_w= (const float*)d_in[12];
    float* out = (float*)d_out;

    float *xzp, *xcp, *xdblp, *deltap, *yp, *featp, *Ap;
    cudaGetSymbolAddress((void**)&xzp, g_xz);
    cudaGetSymbolAddress((void**)&xcp, g_xc);
    cudaGetSymbolAddress((void**)&xdblp, g_xdbl);
    cudaGetSymbolAddress((void**)&deltap, g_delta);
    cudaGetSymbolAddress((void**)&yp, g_y);
    cudaGetSymbolAddress((void**)&featp, g_feat);
    cudaGetSymbolAddress((void**)&Ap, g_A);

    cudaFuncSetAttribute(tc_gemm<1, 0>, cudaFuncAttributeMaxDynamicSharedMemorySize, SMEM_T);
    cudaFuncSetAttribute(tc_gemm<0, 0>, cudaFuncAttributeMaxDynamicSharedMemorySize, SMEM_N);
    cudaFuncSetAttribute(tc_gemm<0, 1>, cudaFuncAttributeMaxDynamicSharedMemorySize, SMEM_N);

    // 1) xz = in_proj
    {
        dim3 grid(LSEQ / 128, E2 / 128, 4);
        tc_gemm<1, 0><<<grid, 256, SMEM_T>>>(in_proj_w, hidden, xzp, E2, LSEQ, DM,
                                             0LL, (long long)LSEQ * DM, (long long)E2 * LSEQ,
                                             (const float*)0);
    }
    // 2) FFT features
    {
        dim3 grid(DI / 32, 32);
        fft_feat_kernel<<<grid, 32>>>(xzp, featp);
    }
    // 3) loss -> out[last]
    loss_kernel<<<1, 256>>>(featp, out, (long long)out_size - 1);
    // 4) A prep
    aprep_kernel<<<1, 256>>>(featp, A_log, Ap);
    // 5) conv + silu
    conv_kernel<<<4 * DI, 256>>>(xzp, conv_w, conv_b, xcp);
    // 6) x_dbl
    {
        dim3 grid(LSEQ / 128, 1, 4);
        tc_gemm<0, 0><<<grid, 256, SMEM_N>>>(x_proj_w, xcp, xdblp, 96, LSEQ, DI,
                                             0LL, (long long)DI * LSEQ, (long long)96 * LSEQ,
                                             (const float*)0);
    }
    // 7) delta (softplus + bias epilogue)
    {
        dim3 grid(LSEQ / 128, DI / 128, 4);
        tc_gemm<0, 1><<<grid, 256, SMEM_N>>>(dt_proj_w, xdblp, deltap, DI, LSEQ, 64,
                                             0LL, (long long)96 * LSEQ, (long long)DI * LSEQ,
                                             dt_proj_b);
    }
    // 8) scan -> y (l,d)
    {
        dim3 grid(DI / 16, 4);
        scan_kernel<<<grid, 256>>>(deltap, xcp, xzp, xdblp, Ap, Dparam, yp);
    }
    // 9) out = y @ out_proj^T
    {
        dim3 grid(DM / 128, LSEQ / 128, 4);
        tc_gemm<1, 0><<<grid, 256, SMEM_T>>>(yp, out_proj_w, out, LSEQ, DM, DI,
                                             (long long)LSEQ * DI, 0LL, (long long)LSEQ * DM,
                                             (const float*)0);
    }
}

// round 6
// speedup vs baseline: 1.9403x; 1.0023x over previous
#include <cuda_runtime.h>
#include <cuda_bf16.h>
#include <math.h>
#include <stdint.h>

#define LSEQ 2048
#define DI   2048
#define DM   1024
#define E2   4096
#define NST  16
#define NBT  32

// ---------------- scratch ----------------
__device__ float g_xz[33554432];    // [4][4096][2048]
__device__ float g_xc[16777216];    // [4][2048][2048]
__device__ float g_xdbl[786432];    // [4][96][2048]
__device__ float g_delta[16777216]; // [4][2048][2048]
__device__ float g_y[16777216];     // [4][2048][2048] (l,d)
__device__ float g_feat[65536];     // [32][2048]
__device__ float g_A[32768];        // [2048][16]
__device__ float g_h[8388608];      // tf32-rounded hidden [4][2048][1024]
__device__ float g_w1[4194304];     // tf32-rounded in_proj_w
__device__ float g_wo[2097152];     // tf32-rounded out_proj_w

__device__ __forceinline__ float softplus_f(float x) {
    return fmaxf(x, 0.f) + log1pf(expf(-fabsf(x)));
}

__device__ __forceinline__ uint32_t f2tf(float f) {
    uint32_t r;
    asm("cvt.rna.tf32.f32 %0, %1;" : "=r"(r) : "f"(f));
    return r;
}

__device__ __forceinline__ void mma_tf32(float c[4], const uint32_t a[4], const uint32_t b[2]) {
    asm volatile(
        "mma.sync.aligned.m16n8k8.row.col.f32.tf32.tf32.f32 "
        "{%0,%1,%2,%3}, {%4,%5,%6,%7}, {%8,%9}, {%0,%1,%2,%3};\n"
        : "+f"(c[0]), "+f"(c[1]), "+f"(c[2]), "+f"(c[3])
        : "r"(a[0]), "r"(a[1]), "r"(a[2]), "r"(a[3]), "r"(b[0]), "r"(b[1]));
}

__device__ __forceinline__ void cp_async16(uint32_t smem_addr, const void* gptr) {
    asm volatile("cp.async.cg.shared.global [%0], [%1], 16;\n" :: "r"(smem_addr), "l"(gptr));
}
__device__ __forceinline__ void cp_commit() {
    asm volatile("cp.async.commit_group;\n");
}
template<int N>
__device__ __forceinline__ void cp_wait() {
    asm volatile("cp.async.wait_group %0;\n" :: "n"(N));
}

__device__ __forceinline__ float blockReduceSum256(float v, float* red, int tid) {
    #pragma unroll
    for (int o = 16; o > 0; o >>= 1) v += __shfl_xor_sync(0xffffffffu, v, o);
    if ((tid & 31) == 0) red[tid >> 5] = v;
    __syncthreads();
    if (tid < 8) {
        float r = red[tid];
        #pragma unroll
        for (int o = 4; o > 0; o >>= 1) r += __shfl_xor_sync(0xffu, r, o);
        if (tid == 0) red[32] = r;
    }
    __syncthreads();
    float out = red[32];
    __syncthreads();
    return out;
}

__device__ __forceinline__ float blockReduceMax256(float v, float* red, int tid) {
    #pragma unroll
    for (int o = 16; o > 0; o >>= 1) v = fmaxf(v, __shfl_xor_sync(0xffffffffu, v, o));
    if ((tid & 31) == 0) red[tid >> 5] = v;
    __syncthreads();
    if (tid < 8) {
        float r = red[tid];
        #pragma unroll
        for (int o = 4; o > 0; o >>= 1) r = fmaxf(r, __shfl_xor_sync(0xffu, r, o));
        if (tid == 0) red[32] = r;
    }
    __syncthreads();
    float out = red[32];
    __syncthreads();
    return out;
}

// ---------------- elementwise tf32 rounding ----------------
__global__ void __launch_bounds__(256) round_tf32_kernel(const float* __restrict__ in,
                                                         float* __restrict__ out, int n4) {
    int i = blockIdx.x * 256 + threadIdx.x;
    if (i < n4) {
        float4 v = ((const float4*)in)[i];
        uint4 r;
        r.x = f2tf(v.x); r.y = f2tf(v.y); r.z = f2tf(v.z); r.w = f2tf(v.w);
        ((uint4*)out)[i] = r;
    }
}

// =====================================================================
// Pipelined TF32 GEMM: block 128x128x32, 3-stage cp.async, 8 warps (2x4)
// TRANSB=1: C[M,N] = A(MxK) * B(NxK)^T
// TRANSB=0: C[M,N] = A(MxK) * B(KxN), ldb=N
// EPI=1: softplus(C + bias[m])
// CVT=1: round fragments to tf32 at load (inputs not pre-rounded)
// =====================================================================
#define APITCH 36
#define BPITCH_NN 136
#define ASZ (128 * APITCH)
#define BSZ_T (128 * APITCH)
#define BSZ_N (32 * BPITCH_NN)
#define STAGES 3

template<int TRANSB, int EPI, int CVT>
__global__ void __launch_bounds__(256) tc_gemm(const float* __restrict__ Ag,
                                               const float* __restrict__ Bg,
                                               float* __restrict__ Cg,
                                               int M, int N, int K,
                                               long long sA, long long sB, long long sC,
                                               const float* __restrict__ bias) {
    extern __shared__ float smem[];
    const int BSZ = TRANSB ? BSZ_T : BSZ_N;
    float* AsBase = smem;
    float* BsBase = smem + STAGES * ASZ;

    const float* A = Ag + (long long)blockIdx.z * sA;
    const float* B = Bg + (long long)blockIdx.z * sB;
    float*       C = Cg + (long long)blockIdx.z * sC;
    const int m0 = blockIdx.y * 128, n0 = blockIdx.x * 128;

    const int tid = threadIdx.x;
    const int wid = tid >> 5, lane = tid & 31;
    const int wm = (wid >> 2) * 64;
    const int wn = (wid & 3) * 32;
    const int g = lane >> 2, tg = lane & 3;

    const int nk = K >> 5;

    auto issue_tile = [&](int s, int kt) {
        if (kt < nk) {
            int k0 = kt << 5;
            float* As = AsBase + s * ASZ;
            float* Bs = BsBase + s * BSZ;
            #pragma unroll
            for (int r = 0; r < 4; r++) {
                int c = tid + r * 256;
                int row = c >> 3;
                int kq = (c & 7) << 2;
                int mrow = m0 + row;
                if (mrow >= M) mrow = M - 1;
                uint32_t dst = (uint32_t)__cvta_generic_to_shared(As + row * APITCH + kq);
                cp_async16(dst, A + (long long)mrow * K + k0 + kq);
            }
            if (TRANSB) {
                #pragma unroll
                for (int r = 0; r < 4; r++) {
                    int c = tid + r * 256;
                    int row = c >> 3;
                    int kq = (c & 7) << 2;
                    uint32_t dst = (uint32_t)__cvta_generic_to_shared(Bs + row * APITCH + kq);
                    cp_async16(dst, B + (long long)(n0 + row) * K + k0 + kq);
                }
            } else {
                #pragma unroll
                for (int r = 0; r < 4; r++) {
                    int c = tid + r * 256;
                    int k = c >> 5;
                    int nq = (c & 31) << 2;
                    uint32_t dst = (uint32_t)__cvta_generic_to_shared(Bs + k * BPITCH_NN + nq);
                    cp_async16(dst, B + (long long)(k0 + k) * N + n0 + nq);
                }
            }
        }
        cp_commit();
    };

    auto frag = [&](const float* p) -> uint32_t {
        if (CVT) return f2tf(*p);
        return *(const uint32_t*)p;
    };

    float c[4][4][4];
    #pragma unroll
    for (int mi = 0; mi < 4; mi++)
        #pragma unroll
        for (int ni = 0; ni < 4; ni++)
            #pragma unroll
            for (int r = 0; r < 4; r++) c[mi][ni][r] = 0.f;

    issue_tile(0, 0);
    issue_tile(1, 1);

    for (int kt = 0; kt < nk; kt++) {
        issue_tile((kt + 2) % STAGES, kt + 2);
        cp_wait<2>();
        __syncthreads();
        const float* As = AsBase + (kt % STAGES) * ASZ;
        const float* Bs = BsBase + (kt % STAGES) * BSZ;

        #pragma unroll
        for (int kk = 0; kk < 32; kk += 8) {
            uint32_t a[4][4], bfr[4][2];
            #pragma unroll
            for (int mi = 0; mi < 4; mi++) {
                const float* Ar = As + (wm + mi * 16 + g) * APITCH + kk + tg;
                a[mi][0] = frag(Ar);
                a[mi][1] = frag(Ar + 8 * APITCH);
                a[mi][2] = frag(Ar + 4);
                a[mi][3] = frag(Ar + 8 * APITCH + 4);
            }
            if (TRANSB) {
                #pragma unroll
                for (int ni = 0; ni < 4; ni++) {
                    const float* Br = Bs + (wn + ni * 8 + g) * APITCH + kk + tg;
                    bfr[ni][0] = frag(Br);
                    bfr[ni][1] = frag(Br + 4);
                }
            } else {
                #pragma unroll
                for (int ni = 0; ni < 4; ni++) {
                    const float* Br = Bs + (kk + tg) * BPITCH_NN + wn + ni * 8 + g;
                    bfr[ni][0] = frag(Br);
                    bfr[ni][1] = frag(Br + 4 * BPITCH_NN);
                }
            }
            #pragma unroll
            for (int mi = 0; mi < 4; mi++)
                #pragma unroll
                for (int ni = 0; ni < 4; ni++)
                    mma_tf32(c[mi][ni], a[mi], bfr[ni]);
        }
        __syncthreads();
    }

    #pragma unroll
    for (int mi = 0; mi < 4; mi++) {
        int r0 = m0 + wm + mi * 16 + g;
        int r1 = r0 + 8;
        float b0v = 0.f, b1v = 0.f;
        if (EPI) {
            if (r0 < M) b0v = bias[r0];
            if (r1 < M) b1v = bias[r1];
        }
        #pragma unroll
        for (int ni = 0; ni < 4; ni++) {
            int col = n0 + wn + ni * 8 + 2 * tg;
            float v0 = c[mi][ni][0], v1 = c[mi][ni][1];
            float v2 = c[mi][ni][2], v3 = c[mi][ni][3];
            if (EPI) {
                v0 = softplus_f(v0 + b0v); v1 = softplus_f(v1 + b0v);
                v2 = softplus_f(v2 + b1v); v3 = softplus_f(v3 + b1v);
            }
            if (r0 < M) *(float2*)(C + (long long)r0 * N + col) = make_float2(v0, v1);
            if (r1 < M) *(float2*)(C + (long long)r1 * N + col) = make_float2(v2, v3);
        }
    }
}

#define SMEM_T ((STAGES * (ASZ + BSZ_T)) * 4)
#define SMEM_N ((STAGES * (ASZ + BSZ_N)) * 4)

// ---------------- FFT channel-alignment features ----------------
__global__ void __launch_bounds__(32) fft_feat_kernel(const float* __restrict__ xz,
                                                      float* __restrict__ feat) {
    __shared__ float sx[256 * 33];
    __shared__ float twc[16], tws[16];
    int tid = threadIdx.x;
    int bt = blockIdx.y;
    int b = bt >> 3, t = bt & 7;
    int c0 = blockIdx.x * 32;
    if (tid < 16) {
        float ang = tid * 0.39269908169872414f;
        twc[tid] = cosf(ang);
        tws[tid] = sinf(ang);
    }
    const float* xb = xz + ((long long)(b * E2 + c0)) * LSEQ + t * 256;
    for (int i = tid; i < 32 * 256; i += 32) {
        int c = i >> 8, l = i & 255;
        sx[l * 33 + c] = xb[(long long)c * LSEQ + l];
    }
    __syncwarp();
    int c = tid;
    float S_tot = 0.f, S_high = 0.f;
    for (int wq = 0; wq < 9; wq++) {
        float Rr[16], Ri[16];
        #pragma unroll
        for (int h = 0; h < 16; h++) {
            float rr = 0.f, ri = 0.f;
            #pragma unroll
            for (int w = 0; w < 16; w++) {
                float v = sx[(h * 16 + w) * 33 + c];
                int id = (w * wq) & 15;
                rr += v * twc[id];
                ri -= v * tws[id];
            }
            Rr[h] = rr; Ri[h] = ri;
        }
        #pragma unroll
        for (int hq = 0; hq < 16; hq++) {
            float fre = 0.f, fim = 0.f;
            #pragma unroll
            for (int h = 0; h < 16; h++) {
                int id = (h * hq) & 15;
                float cc = twc[id], sn = tws[id];
                fre += Rr[h] * cc + Ri[h] * sn;
                fim += Ri[h] * cc - Rr[h] * sn;
            }
            float mag = sqrtf(fre * fre + fim * fim + 1e-8f);
            S_tot += mag;
            int hs = (hq + 8) & 15;
            int ws = wq + 4; if (ws >= 9) ws -= 9;
            float dh = (hs - 8) * (1.0f / 16.0f);
            float dw = (ws - 4) * (1.0f / 9.0f);
            if (dh * dh + dw * dw >= 0.25f) S_high += mag;
        }
    }
    feat[(long long)bt * DI + c0 + c] = S_high / (S_tot + 1e-8f);
}

// ---------------- alignment loss ----------------
__global__ void __launch_bounds__(256) loss_kernel(const float* __restrict__ feat,
                                                   float* __restrict__ out, long long loss_idx) {
    __shared__ float g[DI];
    __shared__ float red[40];
    int tid = threadIdx.x;
    for (int cc = tid; cc < DI; cc += 256) g[cc] = 0.f;
    __syncthreads();
    for (int i = 0; i < NBT; i++) {
        float ss = 0.f;
        for (int cc = tid; cc < DI; cc += 256) {
            float v = feat[i * DI + cc];
            ss += v * v;
        }
        ss = blockReduceSum256(ss, red, tid);
        float inv = 1.f / fmaxf(sqrtf(ss), 1e-12f);
        for (int cc = tid; cc < DI; cc += 256) g[cc] += feat[i * DI + cc] * inv;
        __syncthreads();
    }
    float tt = 0.f;
    for (int cc = tid; cc < DI; cc += 256) tt += g[cc] * g[cc];
    tt = blockReduceSum256(tt, red, tid);
    if (tid == 0) out[loss_idx] = 1.f - tt / (float)(NBT * NBT);
}

// ---------------- A preparation (invert_A) ----------------
__global__ void __launch_bounds__(256) aprep_kernel(const float* __restrict__ feat,
                                                    const float* __restrict__ A_log,
                                                    float* __restrict__ Aout) {
    __shared__ float sf[DI];
    __shared__ float satt[DI];
    __shared__ float red[40];
    __shared__ float wmx[8][16], wmn[8][16];
    __shared__ float colMx[16], colMn[16];
    int tid = threadIdx.x;
    int lane = tid & 31, wid = tid >> 5;
    for (int cc = tid; cc < DI; cc += 256) {
        float s = 0.f;
        for (int i = 0; i < NBT; i++) s += feat[i * DI + cc];
        sf[cc] = s * (1.0f / NBT);
    }
    __syncthreads();
    float mx = -3.4e38f;
    for (int cc = tid; cc < DI; cc += 256) mx = fmaxf(mx, sf[cc]);
    mx = blockReduceMax256(mx, red, tid);
    float se = 0.f;
    for (int cc = tid; cc < DI; cc += 256) {
        float e = expf(sf[cc] - mx);
        sf[cc] = e;
        se += e;
    }
    se = blockReduceSum256(se, red, tid);
    float inv_se = 1.f / se;
    float cm[16], cn[16];
    #pragma unroll
    for (int n = 0; n < 16; n++) { cm[n] = -3.4e38f; cn[n] = 3.4e38f; }
    float am = 0.f;
    for (int d = tid; d < DI; d += 256) {
        float ss = 0.f;
        #pragma unroll
        for (int n = 0; n < 16; n++) {
            float al = A_log[d * 16 + n];
            float e = expf(al);
            ss += e * e;
            cm[n] = fmaxf(cm[n], al);
            cn[n] = fminf(cn[n], al);
        }
        float an = sqrtf(ss);
        satt[d] = an;
        am = fmaxf(am, an);
    }
    am = blockReduceMax256(am, red, tid);
    #pragma unroll
    for (int o = 16; o > 0; o >>= 1) {
        #pragma unroll
        for (int n = 0; n < 16; n++) {
            cm[n] = fmaxf(cm[n], __shfl_xor_sync(0xffffffffu, cm[n], o));
            cn[n] = fminf(cn[n], __shfl_xor_sync(0xffffffffu, cn[n], o));
        }
    }
    if (lane == 0) {
        #pragma unroll
        for (int n = 0; n < 16; n++) { wmx[wid][n] = cm[n]; wmn[wid][n] = cn[n]; }
    }
    __syncthreads();
    if (tid < 16) {
        float m = -3.4e38f, mn = 3.4e38f;
        for (int w = 0; w < 8; w++) { m = fmaxf(m, wmx[w][tid]); mn = fminf(mn, wmn[w][tid]); }
        colMx[tid] = m; colMn[tid] = mn;
    }
    __syncthreads();
    float inv_am = 1.f / (am + 1e-8f);
    for (int i = tid; i < DI * 16; i += 256) {
        int d = i >> 4, n = i & 15;
        float f = sf[d] * inv_se;
        float att = satt[d] * inv_am;
        float alpha = fminf(fmaxf(f * (1.f - att), 0.f), 1.f);
        float al = A_log[i];
        float fl = colMx[n] + colMn[n] - al;
        float an = (1.f - alpha) * al + alpha * fl;
        Aout[i] = -expf(an);
    }
}

// ---------------- causal depthwise conv (width 4) + silu ----------------
__global__ void __launch_bounds__(256) conv_kernel(const float* __restrict__ xz,
                                                   const float* __restrict__ cw,
                                                   const float* __restrict__ cb,
                                                   float* __restrict__ xc) {
    __shared__ float row[LSEQ + 3];
    int rid = blockIdx.x;
    int b = rid >> 11, d = rid & 2047;
    int tid = threadIdx.x;
    const float* xp = xz + ((long long)b * E2 + d) * LSEQ;
    if (tid < 3) row[tid] = 0.f;
    for (int i = tid; i < LSEQ; i += 256) row[3 + i] = xp[i];
    __syncthreads();
    float w0 = cw[d * 4 + 0], w1 = cw[d * 4 + 1], w2 = cw[d * 4 + 2], w3 = cw[d * 4 + 3];
    float bb = cb[d];
    float* op = xc + ((long long)b * DI + d) * LSEQ;
    for (int i = tid; i < LSEQ; i += 256) {
        float v = bb + w0 * row[i] + w1 * row[i + 1] + w2 * row[i + 2] + w3 * row[i + 3];
        op[i] = v / (1.f + expf(-v));
    }
}

// ---------------- selective scan (y written tf32-rounded) ----------------
__global__ void __launch_bounds__(256) scan_kernel(const float* __restrict__ delta,
                                                   const float* __restrict__ xc,
                                                   const float* __restrict__ xz,
                                                   const float* __restrict__ xdbl,
                                                   const float* __restrict__ A,
                                                   const float* __restrict__ Dp,
                                                   float* __restrict__ y) {
    __shared__ float sDel[64][17], sU[64][17], sZ[64][17];
    __shared__ float sB[64][17], sC[64][17], sY[64][17];
    int tid = threadIdx.x;
    int ci = tid >> 4, n = tid & 15;
    int b = blockIdx.y;
    int d0 = blockIdx.x * 16;
    int d = d0 + ci;
    const float* delp = delta + ((long long)b * DI + d0) * LSEQ;
    const float* up   = xc    + ((long long)b * DI + d0) * LSEQ;
    const float* zp   = xz    + ((long long)b * E2 + DI + d0) * LSEQ;
    const float* bp   = xdbl  + ((long long)b * 96 + 64) * LSEQ;
    const float* cp   = xdbl  + ((long long)b * 96 + 80) * LSEQ;
    float*       yp   = y     + (long long)b * LSEQ * DI;
    float a = A[d * 16 + n];
    float dD = Dp[d];
    float s = 0.f;
    for (int l0 = 0; l0 < LSEQ; l0 += 64) {
        for (int i = tid; i < 1024; i += 256) {
            int cc = i >> 6, j = i & 63;
            sDel[j][cc] = delp[(long long)cc * LSEQ + l0 + j];
            sU[j][cc]   = up[(long long)cc * LSEQ + l0 + j];
            sZ[j][cc]   = zp[(long long)cc * LSEQ + l0 + j];
            sB[j][cc]   = bp[(long long)cc * LSEQ + l0 + j];
            sC[j][cc]   = cp[(long long)cc * LSEQ + l0 + j];
        }
        __syncthreads();
        #pragma unroll 4
        for (int j = 0; j < 64; j++) {
            float dl = sDel[j][ci];
            float u  = sU[j][ci];
            float bb = sB[j][n];
            float ccv = sC[j][n];
            s = s * __expf(dl * a) + (dl * u) * bb;
            float p = s * ccv;
            #pragma unroll
            for (int o = 8; o > 0; o >>= 1) p += __shfl_xor_sync(0xffffffffu, p, o, 16);
            if (n == 0) {
                float z = sZ[j][ci];
                float yy = (p + u * dD) * (z / (1.f + __expf(-z)));
                sY[j][ci] = __uint_as_float(f2tf(yy));   // pre-round for out_proj GEMM
            }
        }
        __syncthreads();
        for (int i = tid; i < 1024; i += 256) {
            int j = i >> 4, cc = i & 15;
            yp[(long long)(l0 + j) * DI + d0 + cc] = sY[j][cc];
        }
        __syncthreads();
    }
}

// ---------------- launch ----------------
extern "C" void kernel_launch(void* const* d_in, const int* in_sizes, int n_in,
                              void* d_out, int out_size) {
    const float* hidden    = (const float*)d_in[0];
    const float* in_proj_w = (const float*)d_in[4];
    const float* conv_w    = (const float*)d_in[5];
    const float* conv_b    = (const float*)d_in[6];
    const float* x_proj_w  = (const float*)d_in[7];
    const float* dt_proj_w = (const float*)d_in[8];
    const float* dt_proj_b = (const float*)d_in[9];
    const float* A_log     = (const float*)d_in[10];
    const float* Dparam    = (const float*)d_in[11];
    const float* out_proj_w= (const float*)d_in[12];
    float* out = (float*)d_out;

    float *xzp, *xcp, *xdblp, *deltap, *yp, *featp, *Ap, *hp, *w1p, *wop;
    cudaGetSymbolAddress((void**)&xzp, g_xz);
    cudaGetSymbolAddress((void**)&xcp, g_xc);
    cudaGetSymbolAddress((void**)&xdblp, g_xdbl);
    cudaGetSymbolAddress((void**)&deltap, g_delta);
    cudaGetSymbolAddress((void**)&yp, g_y);
    cudaGetSymbolAddress((void**)&featp, g_feat);
    cudaGetSymbolAddress((void**)&Ap, g_A);
    cudaGetSymbolAddress((void**)&hp, g_h);
    cudaGetSymbolAddress((void**)&w1p, g_w1);
    cudaGetSymbolAddress((void**)&wop, g_wo);

    cudaFuncSetAttribute(tc_gemm<1, 0, 0>, cudaFuncAttributeMaxDynamicSharedMemorySize, SMEM_T);
    cudaFuncSetAttribute(tc_gemm<0, 0, 1>, cudaFuncAttributeMaxDynamicSharedMemorySize, SMEM_N);
    cudaFuncSetAttribute(tc_gemm<0, 1, 1>, cudaFuncAttributeMaxDynamicSharedMemorySize, SMEM_N);

    // 0) pre-round GEMM operands to tf32 (bit-identical to in-loop cvt)
    round_tf32_kernel<<<(8388608 / 4 + 255) / 256, 256>>>(hidden, hp, 8388608 / 4);
    round_tf32_kernel<<<(4194304 / 4 + 255) / 256, 256>>>(in_proj_w, w1p, 4194304 / 4);
    round_tf32_kernel<<<(2097152 / 4 + 255) / 256, 256>>>(out_proj_w, wop, 2097152 / 4);

    // 1) xz = in_proj (pre-rounded operands, no in-loop cvt)
    {
        dim3 grid(LSEQ / 128, E2 / 128, 4);
        tc_gemm<1, 0, 0><<<grid, 256, SMEM_T>>>(w1p, hp, xzp, E2, LSEQ, DM,
                                                0LL, (long long)LSEQ * DM, (long long)E2 * LSEQ,
                                                (const float*)0);
    }
    // 2) FFT features
    {
        dim3 grid(DI / 32, 32);
        fft_feat_kernel<<<grid, 32>>>(xzp, featp);
    }
    // 3) loss -> out[last]
    loss_kernel<<<1, 256>>>(featp, out, (long long)out_size - 1);
    // 4) A prep
    aprep_kernel<<<1, 256>>>(featp, A_log, Ap);
    // 5) conv + silu
    conv_kernel<<<4 * DI, 256>>>(xzp, conv_w, conv_b, xcp);
    // 6) x_dbl (small; keep in-loop cvt)
    {
        dim3 grid(LSEQ / 128, 1, 4);
        tc_gemm<0, 0, 1><<<grid, 256, SMEM_N>>>(x_proj_w, xcp, xdblp, 96, LSEQ, DI,
                                                0LL, (long long)DI * LSEQ, (long long)96 * LSEQ,
                                                (const float*)0);
    }
    // 7) delta (softplus + bias epilogue; in-loop cvt)
    {
        dim3 grid(LSEQ / 128, DI / 128, 4);
        tc_gemm<0, 1, 1><<<grid, 256, SMEM_N>>>(dt_proj_w, xdblp, deltap, DI, LSEQ, 64,
                                                0LL, (long long)96 * LSEQ, (long long)DI * LSEQ,
                                                dt_proj_b);
    }
    // 8) scan -> y (l,d) tf32-rounded
    {
        dim3 grid(DI / 16, 4);
        scan_kernel<<<grid, 256>>>(deltap, xcp, xzp, xdblp, Ap, Dparam, yp);
    }
    // 9) out = y @ out_proj^T (pre-rounded operands)
    {
        dim3 grid(DM / 128, LSEQ / 128, 4);
        tc_gemm<1, 0, 0><<<grid, 256, SMEM_T>>>(yp, wop, out, LSEQ, DM, DI,
                                                (long long)LSEQ * DI, 0LL, (long long)LSEQ * DM,
                                                (const float*)0);
    }
}

// round 7
// speedup vs baseline: 1.9588x; 1.0095x over previous
#include <cuda_runtime.h>
#include <cuda_bf16.h>
#include <math.h>
#include <stdint.h>

#define LSEQ 2048
#define DI   2048
#define DM   1024
#define E2   4096
#define NST  16
#define NBT  32

// ---------------- scratch ----------------
__device__ float g_xz[33554432];    // [4][4096][2048]
__device__ float g_xc[16777216];    // [4][2048][2048]
__device__ float g_xdbl[786432];    // [4][96][2048]
__device__ float g_delta[16777216]; // [4][2048][2048]
__device__ float g_y[16777216];     // [4][2048][2048] (l,d)
__device__ float g_feat[65536];     // [32][2048]
__device__ float g_A[32768];        // [2048][16]
__device__ float g_h[8388608];      // tf32-rounded hidden
__device__ float g_w1[4194304];     // tf32-rounded in_proj_w
__device__ float g_wo[2097152];     // tf32-rounded out_proj_w

__device__ __forceinline__ float softplus_f(float x) {
    return fmaxf(x, 0.f) + log1pf(expf(-fabsf(x)));
}

__device__ __forceinline__ uint32_t f2tf(float f) {
    uint32_t r;
    asm("cvt.rna.tf32.f32 %0, %1;" : "=r"(r) : "f"(f));
    return r;
}

__device__ __forceinline__ void mma_tf32(float c[4], const uint32_t a[4], const uint32_t b[2]) {
    asm volatile(
        "mma.sync.aligned.m16n8k8.row.col.f32.tf32.tf32.f32 "
        "{%0,%1,%2,%3}, {%4,%5,%6,%7}, {%8,%9}, {%0,%1,%2,%3};\n"
        : "+f"(c[0]), "+f"(c[1]), "+f"(c[2]), "+f"(c[3])
        : "r"(a[0]), "r"(a[1]), "r"(a[2]), "r"(a[3]), "r"(b[0]), "r"(b[1]));
}

__device__ __forceinline__ void cp_async16(uint32_t smem_addr, const void* gptr) {
    asm volatile("cp.async.cg.shared.global [%0], [%1], 16;\n" :: "r"(smem_addr), "l"(gptr));
}
__device__ __forceinline__ void cp_commit() {
    asm volatile("cp.async.commit_group;\n");
}
template<int N>
__device__ __forceinline__ void cp_wait() {
    asm volatile("cp.async.wait_group %0;\n" :: "n"(N));
}

__device__ __forceinline__ float blockReduceSum256(float v, float* red, int tid) {
    #pragma unroll
    for (int o = 16; o > 0; o >>= 1) v += __shfl_xor_sync(0xffffffffu, v, o);
    if ((tid & 31) == 0) red[tid >> 5] = v;
    __syncthreads();
    if (tid < 8) {
        float r = red[tid];
        #pragma unroll
        for (int o = 4; o > 0; o >>= 1) r += __shfl_xor_sync(0xffu, r, o);
        if (tid == 0) red[32] = r;
    }
    __syncthreads();
    float out = red[32];
    __syncthreads();
    return out;
}

__device__ __forceinline__ float blockReduceMax256(float v, float* red, int tid) {
    #pragma unroll
    for (int o = 16; o > 0; o >>= 1) v = fmaxf(v, __shfl_xor_sync(0xffffffffu, v, o));
    if ((tid & 31) == 0) red[tid >> 5] = v;
    __syncthreads();
    if (tid < 8) {
        float r = red[tid];
        #pragma unroll
        for (int o = 4; o > 0; o >>= 1) r = fmaxf(r, __shfl_xor_sync(0xffu, r, o));
        if (tid == 0) red[32] = r;
    }
    __syncthreads();
    float out = red[32];
    __syncthreads();
    return out;
}

// ---------------- elementwise tf32 rounding ----------------
__global__ void __launch_bounds__(256) round_tf32_kernel(const float* __restrict__ in,
                                                         float* __restrict__ out, int n4) {
    int i = blockIdx.x * 256 + threadIdx.x;
    if (i < n4) {
        float4 v = ((const float4*)in)[i];
        uint4 r;
        r.x = f2tf(v.x); r.y = f2tf(v.y); r.z = f2tf(v.z); r.w = f2tf(v.w);
        ((uint4*)out)[i] = r;
    }
}

// =====================================================================
// Pipelined TF32 GEMM: block 128x128x32, 2-stage cp.async, 8 warps (2x4)
// 2 stages -> 72KB smem -> 2 blocks/SM (16 warps) for latency hiding.
// =====================================================================
#define APITCH 36
#define BPITCH_NN 136
#define ASZ (128 * APITCH)
#define BSZ_T (128 * APITCH)
#define BSZ_N (32 * BPITCH_NN)
#define STAGES 2

template<int TRANSB, int EPI, int CVT>
__global__ void __launch_bounds__(256) tc_gemm(const float* __restrict__ Ag,
                                               const float* __restrict__ Bg,
                                               float* __restrict__ Cg,
                                               int M, int N, int K,
                                               long long sA, long long sB, long long sC,
                                               const float* __restrict__ bias) {
    extern __shared__ float smem[];
    const int BSZ = TRANSB ? BSZ_T : BSZ_N;
    float* AsBase = smem;
    float* BsBase = smem + STAGES * ASZ;

    const float* A = Ag + (long long)blockIdx.z * sA;
    const float* B = Bg + (long long)blockIdx.z * sB;
    float*       C = Cg + (long long)blockIdx.z * sC;
    const int m0 = blockIdx.y * 128, n0 = blockIdx.x * 128;

    const int tid = threadIdx.x;
    const int wid = tid >> 5, lane = tid & 31;
    const int wm = (wid >> 2) * 64;
    const int wn = (wid & 3) * 32;
    const int g = lane >> 2, tg = lane & 3;

    const int nk = K >> 5;

    auto issue_tile = [&](int s, int kt) {
        if (kt < nk) {
            int k0 = kt << 5;
            float* As = AsBase + s * ASZ;
            float* Bs = BsBase + s * BSZ;
            #pragma unroll
            for (int r = 0; r < 4; r++) {
                int c = tid + r * 256;
                int row = c >> 3;
                int kq = (c & 7) << 2;
                int mrow = m0 + row;
                if (mrow >= M) mrow = M - 1;
                uint32_t dst = (uint32_t)__cvta_generic_to_shared(As + row * APITCH + kq);
                cp_async16(dst, A + (long long)mrow * K + k0 + kq);
            }
            if (TRANSB) {
                #pragma unroll
                for (int r = 0; r < 4; r++) {
                    int c = tid + r * 256;
                    int row = c >> 3;
                    int kq = (c & 7) << 2;
                    uint32_t dst = (uint32_t)__cvta_generic_to_shared(Bs + row * APITCH + kq);
                    cp_async16(dst, B + (long long)(n0 + row) * K + k0 + kq);
                }
            } else {
                #pragma unroll
                for (int r = 0; r < 4; r++) {
                    int c = tid + r * 256;
                    int k = c >> 5;
                    int nq = (c & 31) << 2;
                    uint32_t dst = (uint32_t)__cvta_generic_to_shared(Bs + k * BPITCH_NN + nq);
                    cp_async16(dst, B + (long long)(k0 + k) * N + n0 + nq);
                }
            }
        }
        cp_commit();
    };

    auto frag = [&](const float* p) -> uint32_t {
        if (CVT) return f2tf(*p);
        return *(const uint32_t*)p;
    };

    float c[4][4][4];
    #pragma unroll
    for (int mi = 0; mi < 4; mi++)
        #pragma unroll
        for (int ni = 0; ni < 4; ni++)
            #pragma unroll
            for (int r = 0; r < 4; r++) c[mi][ni][r] = 0.f;

    issue_tile(0, 0);

    for (int kt = 0; kt < nk; kt++) {
        issue_tile((kt + 1) % STAGES, kt + 1);
        cp_wait<1>();
        __syncthreads();
        const float* As = AsBase + (kt % STAGES) * ASZ;
        const float* Bs = BsBase + (kt % STAGES) * BSZ;

        #pragma unroll
        for (int kk = 0; kk < 32; kk += 8) {
            uint32_t a[4][4], bfr[4][2];
            #pragma unroll
            for (int mi = 0; mi < 4; mi++) {
                const float* Ar = As + (wm + mi * 16 + g) * APITCH + kk + tg;
                a[mi][0] = frag(Ar);
                a[mi][1] = frag(Ar + 8 * APITCH);
                a[mi][2] = frag(Ar + 4);
                a[mi][3] = frag(Ar + 8 * APITCH + 4);
            }
            if (TRANSB) {
                #pragma unroll
                for (int ni = 0; ni < 4; ni++) {
                    const float* Br = Bs + (wn + ni * 8 + g) * APITCH + kk + tg;
                    bfr[ni][0] = frag(Br);
                    bfr[ni][1] = frag(Br + 4);
                }
            } else {
                #pragma unroll
                for (int ni = 0; ni < 4; ni++) {
                    const float* Br = Bs + (kk + tg) * BPITCH_NN + wn + ni * 8 + g;
                    bfr[ni][0] = frag(Br);
                    bfr[ni][1] = frag(Br + 4 * BPITCH_NN);
                }
            }
            #pragma unroll
            for (int mi = 0; mi < 4; mi++)
                #pragma unroll
                for (int ni = 0; ni < 4; ni++)
                    mma_tf32(c[mi][ni], a[mi], bfr[ni]);
        }
        __syncthreads();
    }

    #pragma unroll
    for (int mi = 0; mi < 4; mi++) {
        int r0 = m0 + wm + mi * 16 + g;
        int r1 = r0 + 8;
        float b0v = 0.f, b1v = 0.f;
        if (EPI) {
            if (r0 < M) b0v = bias[r0];
            if (r1 < M) b1v = bias[r1];
        }
        #pragma unroll
        for (int ni = 0; ni < 4; ni++) {
            int col = n0 + wn + ni * 8 + 2 * tg;
            float v0 = c[mi][ni][0], v1 = c[mi][ni][1];
            float v2 = c[mi][ni][2], v3 = c[mi][ni][3];
            if (EPI) {
                v0 = softplus_f(v0 + b0v); v1 = softplus_f(v1 + b0v);
                v2 = softplus_f(v2 + b1v); v3 = softplus_f(v3 + b1v);
            }
            if (r0 < M) *(float2*)(C + (long long)r0 * N + col) = make_float2(v0, v1);
            if (r1 < M) *(float2*)(C + (long long)r1 * N + col) = make_float2(v2, v3);
        }
    }
}

#define SMEM_T ((STAGES * (ASZ + BSZ_T)) * 4)
#define SMEM_N ((STAGES * (ASZ + BSZ_N)) * 4)

// ---------------- FFT channel-alignment features ----------------
__global__ void __launch_bounds__(32) fft_feat_kernel(const float* __restrict__ xz,
                                                      float* __restrict__ feat) {
    __shared__ float sx[256 * 33];
    __shared__ float twc[16], tws[16];
    int tid = threadIdx.x;
    int bt = blockIdx.y;
    int b = bt >> 3, t = bt & 7;
    int c0 = blockIdx.x * 32;
    if (tid < 16) {
        float ang = tid * 0.39269908169872414f;
        twc[tid] = cosf(ang);
        tws[tid] = sinf(ang);
    }
    const float* xb = xz + ((long long)(b * E2 + c0)) * LSEQ + t * 256;
    for (int i = tid; i < 32 * 256; i += 32) {
        int c = i >> 8, l = i & 255;
        sx[l * 33 + c] = xb[(long long)c * LSEQ + l];
    }
    __syncwarp();
    int c = tid;
    float S_tot = 0.f, S_high = 0.f;
    for (int wq = 0; wq < 9; wq++) {
        float Rr[16], Ri[16];
        #pragma unroll
        for (int h = 0; h < 16; h++) {
            float rr = 0.f, ri = 0.f;
            #pragma unroll
            for (int w = 0; w < 16; w++) {
                float v = sx[(h * 16 + w) * 33 + c];
                int id = (w * wq) & 15;
                rr += v * twc[id];
                ri -= v * tws[id];
            }
            Rr[h] = rr; Ri[h] = ri;
        }
        #pragma unroll
        for (int hq = 0; hq < 16; hq++) {
            float fre = 0.f, fim = 0.f;
            #pragma unroll
            for (int h = 0; h < 16; h++) {
                int id = (h * hq) & 15;
                float cc = twc[id], sn = tws[id];
                fre += Rr[h] * cc + Ri[h] * sn;
                fim += Ri[h] * cc - Rr[h] * sn;
            }
            float mag = sqrtf(fre * fre + fim * fim + 1e-8f);
            S_tot += mag;
            int hs = (hq + 8) & 15;
            int ws = wq + 4; if (ws >= 9) ws -= 9;
            float dh = (hs - 8) * (1.0f / 16.0f);
            float dw = (ws - 4) * (1.0f / 9.0f);
            if (dh * dh + dw * dw >= 0.25f) S_high += mag;
        }
    }
    feat[(long long)bt * DI + c0 + c] = S_high / (S_tot + 1e-8f);
}

// ---------------- alignment loss ----------------
__global__ void __launch_bounds__(256) loss_kernel(const float* __restrict__ feat,
                                                   float* __restrict__ out, long long loss_idx) {
    __shared__ float g[DI];
    __shared__ float red[40];
    int tid = threadIdx.x;
    for (int cc = tid; cc < DI; cc += 256) g[cc] = 0.f;
    __syncthreads();
    for (int i = 0; i < NBT; i++) {
        float ss = 0.f;
        for (int cc = tid; cc < DI; cc += 256) {
            float v = feat[i * DI + cc];
            ss += v * v;
        }
        ss = blockReduceSum256(ss, red, tid);
        float inv = 1.f / fmaxf(sqrtf(ss), 1e-12f);
        for (int cc = tid; cc < DI; cc += 256) g[cc] += feat[i * DI + cc] * inv;
        __syncthreads();
    }
    float tt = 0.f;
    for (int cc = tid; cc < DI; cc += 256) tt += g[cc] * g[cc];
    tt = blockReduceSum256(tt, red, tid);
    if (tid == 0) out[loss_idx] = 1.f - tt / (float)(NBT * NBT);
}

// ---------------- A preparation (invert_A) ----------------
__global__ void __launch_bounds__(256) aprep_kernel(const float* __restrict__ feat,
                                                    const float* __restrict__ A_log,
                                                    float* __restrict__ Aout) {
    __shared__ float sf[DI];
    __shared__ float satt[DI];
    __shared__ float red[40];
    __shared__ float wmx[8][16], wmn[8][16];
    __shared__ float colMx[16], colMn[16];
    int tid = threadIdx.x;
    int lane = tid & 31, wid = tid >> 5;
    for (int cc = tid; cc < DI; cc += 256) {
        float s = 0.f;
        for (int i = 0; i < NBT; i++) s += feat[i * DI + cc];
        sf[cc] = s * (1.0f / NBT);
    }
    __syncthreads();
    float mx = -3.4e38f;
    for (int cc = tid; cc < DI; cc += 256) mx = fmaxf(mx, sf[cc]);
    mx = blockReduceMax256(mx, red, tid);
    float se = 0.f;
    for (int cc = tid; cc < DI; cc += 256) {
        float e = expf(sf[cc] - mx);
        sf[cc] = e;
        se += e;
    }
    se = blockReduceSum256(se, red, tid);
    float inv_se = 1.f / se;
    float cm[16], cn[16];
    #pragma unroll
    for (int n = 0; n < 16; n++) { cm[n] = -3.4e38f; cn[n] = 3.4e38f; }
    float am = 0.f;
    for (int d = tid; d < DI; d += 256) {
        float ss = 0.f;
        #pragma unroll
        for (int n = 0; n < 16; n++) {
            float al = A_log[d * 16 + n];
            float e = expf(al);
            ss += e * e;
            cm[n] = fmaxf(cm[n], al);
            cn[n] = fminf(cn[n], al);
        }
        float an = sqrtf(ss);
        satt[d] = an;
        am = fmaxf(am, an);
    }
    am = blockReduceMax256(am, red, tid);
    #pragma unroll
    for (int o = 16; o > 0; o >>= 1) {
        #pragma unroll
        for (int n = 0; n < 16; n++) {
            cm[n] = fmaxf(cm[n], __shfl_xor_sync(0xffffffffu, cm[n], o));
            cn[n] = fminf(cn[n], __shfl_xor_sync(0xffffffffu, cn[n], o));
        }
    }
    if (lane == 0) {
        #pragma unroll
        for (int n = 0; n < 16; n++) { wmx[wid][n] = cm[n]; wmn[wid][n] = cn[n]; }
    }
    __syncthreads();
    if (tid < 16) {
        float m = -3.4e38f, mn = 3.4e38f;
        for (int w = 0; w < 8; w++) { m = fmaxf(m, wmx[w][tid]); mn = fminf(mn, wmn[w][tid]); }
        colMx[tid] = m; colMn[tid] = mn;
    }
    __syncthreads();
    float inv_am = 1.f / (am + 1e-8f);
    for (int i = tid; i < DI * 16; i += 256) {
        int d = i >> 4, n = i & 15;
        float f = sf[d] * inv_se;
        float att = satt[d] * inv_am;
        float alpha = fminf(fmaxf(f * (1.f - att), 0.f), 1.f);
        float al = A_log[i];
        float fl = colMx[n] + colMn[n] - al;
        float an = (1.f - alpha) * al + alpha * fl;
        Aout[i] = -expf(an);
    }
}

// ---------------- causal depthwise conv (width 4) + silu ----------------
__global__ void __launch_bounds__(256) conv_kernel(const float* __restrict__ xz,
                                                   const float* __restrict__ cw,
                                                   const float* __restrict__ cb,
                                                   float* __restrict__ xc) {
    __shared__ float row[LSEQ + 3];
    int rid = blockIdx.x;
    int b = rid >> 11, d = rid & 2047;
    int tid = threadIdx.x;
    const float* xp = xz + ((long long)b * E2 + d) * LSEQ;
    if (tid < 3) row[tid] = 0.f;
    for (int i = tid; i < LSEQ; i += 256) row[3 + i] = xp[i];
    __syncthreads();
    float w0 = cw[d * 4 + 0], w1 = cw[d * 4 + 1], w2 = cw[d * 4 + 2], w3 = cw[d * 4 + 3];
    float bb = cb[d];
    float* op = xc + ((long long)b * DI + d) * LSEQ;
    for (int i = tid; i < LSEQ; i += 256) {
        float v = bb + w0 * row[i] + w1 * row[i + 1] + w2 * row[i + 2] + w3 * row[i + 3];
        op[i] = v / (1.f + expf(-v));
    }
}

// ---------------- selective scan (y written tf32-rounded) ----------------
__global__ void __launch_bounds__(256) scan_kernel(const float* __restrict__ delta,
                                                   const float* __restrict__ xc,
                                                   const float* __restrict__ xz,
                                                   const float* __restrict__ xdbl,
                                                   const float* __restrict__ A,
                                                   const float* __restrict__ Dp,
                                                   float* __restrict__ y) {
    __shared__ float sDel[64][17], sU[64][17], sZ[64][17];
    __shared__ float sB[64][17], sC[64][17], sY[64][17];
    int tid = threadIdx.x;
    int ci = tid >> 4, n = tid & 15;
    int b = blockIdx.y;
    int d0 = blockIdx.x * 16;
    int d = d0 + ci;
    const float* delp = delta + ((long long)b * DI + d0) * LSEQ;
    const float* up   = xc    + ((long long)b * DI + d0) * LSEQ;
    const float* zp   = xz    + ((long long)b * E2 + DI + d0) * LSEQ;
    const float* bp   = xdbl  + ((long long)b * 96 + 64) * LSEQ;
    const float* cp   = xdbl  + ((long long)b * 96 + 80) * LSEQ;
    float*       yp   = y     + (long long)b * LSEQ * DI;
    float a = A[d * 16 + n];
    float dD = Dp[d];
    float s = 0.f;
    for (int l0 = 0; l0 < LSEQ; l0 += 64) {
        for (int i = tid; i < 1024; i += 256) {
            int cc = i >> 6, j = i & 63;
            sDel[j][cc] = delp[(long long)cc * LSEQ + l0 + j];
            sU[j][cc]   = up[(long long)cc * LSEQ + l0 + j];
            sZ[j][cc]   = zp[(long long)cc * LSEQ + l0 + j];
            sB[j][cc]   = bp[(long long)cc * LSEQ + l0 + j];
            sC[j][cc]   = cp[(long long)cc * LSEQ + l0 + j];
        }
        __syncthreads();
        #pragma unroll 4
        for (int j = 0; j < 64; j++) {
            float dl = sDel[j][ci];
            float u  = sU[j][ci];
            float bb = sB[j][n];
            float ccv = sC[j][n];
            s = s * __expf(dl * a) + (dl * u) * bb;
            float p = s * ccv;
            #pragma unroll
            for (int o = 8; o > 0; o >>= 1) p += __shfl_xor_sync(0xffffffffu, p, o, 16);
            if (n == 0) {
                float z = sZ[j][ci];
                float yy = (p + u * dD) * (z / (1.f + __expf(-z)));
                sY[j][ci] = __uint_as_float(f2tf(yy));
            }
        }
        __syncthreads();
        for (int i = tid; i < 1024; i += 256) {
            int j = i >> 4, cc = i & 15;
            yp[(long long)(l0 + j) * DI + d0 + cc] = sY[j][cc];
        }
        __syncthreads();
    }
}

// ---------------- launch ----------------
extern "C" void kernel_launch(void* const* d_in, const int* in_sizes, int n_in,
                              void* d_out, int out_size) {
    const float* hidden    = (const float*)d_in[0];
    const float* in_proj_w = (const float*)d_in[4];
    const float* conv_w    = (const float*)d_in[5];
    const float* conv_b    = (const float*)d_in[6];
    const float* x_proj_w  = (const float*)d_in[7];
    const float* dt_proj_w = (const float*)d_in[8];
    const float* dt_proj_b = (const float*)d_in[9];
    const float* A_log     = (const float*)d_in[10];
    const float* Dparam    = (const float*)d_in[11];
    const float* out_proj_w= (const float*)d_in[12];
    float* out = (float*)d_out;

    float *xzp, *xcp, *xdblp, *deltap, *yp, *featp, *Ap, *hp, *w1p, *wop;
    cudaGetSymbolAddress((void**)&xzp, g_xz);
    cudaGetSymbolAddress((void**)&xcp, g_xc);
    cudaGetSymbolAddress((void**)&xdblp, g_xdbl);
    cudaGetSymbolAddress((void**)&deltap, g_delta);
    cudaGetSymbolAddress((void**)&yp, g_y);
    cudaGetSymbolAddress((void**)&featp, g_feat);
    cudaGetSymbolAddress((void**)&Ap, g_A);
    cudaGetSymbolAddress((void**)&hp, g_h);
    cudaGetSymbolAddress((void**)&w1p, g_w1);
    cudaGetSymbolAddress((void**)&wop, g_wo);

    cudaFuncSetAttribute(tc_gemm<1, 0, 0>, cudaFuncAttributeMaxDynamicSharedMemorySize, SMEM_T);
    cudaFuncSetAttribute(tc_gemm<0, 0, 1>, cudaFuncAttributeMaxDynamicSharedMemorySize, SMEM_N);
    cudaFuncSetAttribute(tc_gemm<0, 1, 1>, cudaFuncAttributeMaxDynamicSharedMemorySize, SMEM_N);

    // 0) pre-round GEMM operands to tf32
    round_tf32_kernel<<<(8388608 / 4 + 255) / 256, 256>>>(hidden, hp, 8388608 / 4);
    round_tf32_kernel<<<(4194304 / 4 + 255) / 256, 256>>>(in_proj_w, w1p, 4194304 / 4);
    round_tf32_kernel<<<(2097152 / 4 + 255) / 256, 256>>>(out_proj_w, wop, 2097152 / 4);

    // 1) xz = in_proj
    {
        dim3 grid(LSEQ / 128, E2 / 128, 4);
        tc_gemm<1, 0, 0><<<grid, 256, SMEM_T>>>(w1p, hp, xzp, E2, LSEQ, DM,
                                                0LL, (long long)LSEQ * DM, (long long)E2 * LSEQ,
                                                (const float*)0);
    }
    // 2) FFT features
    {
        dim3 grid(DI / 32, 32);
        fft_feat_kernel<<<grid, 32>>>(xzp, featp);
    }
    // 3) loss -> out[last]
    loss_kernel<<<1, 256>>>(featp, out, (long long)out_size - 1);
    // 4) A prep
    aprep_kernel<<<1, 256>>>(featp, A_log, Ap);
    // 5) conv + silu
    conv_kernel<<<4 * DI, 256>>>(xzp, conv_w, conv_b, xcp);
    // 6) x_dbl
    {
        dim3 grid(LSEQ / 128, 1, 4);
        tc_gemm<0, 0, 1><<<grid, 256, SMEM_N>>>(x_proj_w, xcp, xdblp, 96, LSEQ, DI,
                                                0LL, (long long)DI * LSEQ, (long long)96 * LSEQ,
                                                (const float*)0);
    }
    // 7) delta
    {
        dim3 grid(LSEQ / 128, DI / 128, 4);
        tc_gemm<0, 1, 1><<<grid, 256, SMEM_N>>>(dt_proj_w, xdblp, deltap, DI, LSEQ, 64,
                                                0LL, (long long)96 * LSEQ, (long long)DI * LSEQ,
                                                dt_proj_b);
    }
    // 8) scan -> y
    {
        dim3 grid(DI / 16, 4);
        scan_kernel<<<grid, 256>>>(deltap, xcp, xzp, xdblp, Ap, Dparam, yp);
    }
    // 9) out = y @ out_proj^T
    {
        dim3 grid(DM / 128, LSEQ / 128, 4);
        tc_gemm<1, 0, 0><<<grid, 256, SMEM_T>>>(yp, wop, out, LSEQ, DM, DI,
                                                (long long)LSEQ * DI, 0LL, (long long)LSEQ * DM,
                                                (const float*)0);
    }
}

// round 8
// speedup vs baseline: 2.0876x; 1.0657x over previous
#include <cuda_runtime.h>
#include <cuda_bf16.h>
#include <math.h>
#include <stdint.h>

#define LSEQ 2048
#define DI   2048
#define DM   1024
#define E2   4096
#define NST  16
#define NBT  32

// ---------------- scratch ----------------
__device__ float g_xz[33554432];    // [4][4096][2048]
__device__ float g_xc[16777216];    // [4][2048][2048]
__device__ float g_xdbl[786432];    // [4][96][2048]
__device__ float g_delta[16777216]; // [4][2048][2048]
__device__ float g_y[16777216];     // [4][2048][2048] (l,d)
__device__ float g_feat[65536];     // [32][2048]
__device__ float g_A[32768];        // [2048][16]
__device__ float g_h[8388608];      // tf32-rounded hidden
__device__ float g_w1[4194304];     // tf32-rounded in_proj_w
__device__ float g_wo[2097152];     // tf32-rounded out_proj_w

__device__ __forceinline__ float softplus_f(float x) {
    return fmaxf(x, 0.f) + log1pf(expf(-fabsf(x)));
}

__device__ __forceinline__ uint32_t f2tf(float f) {
    uint32_t r;
    asm("cvt.rna.tf32.f32 %0, %1;" : "=r"(r) : "f"(f));
    return r;
}

__device__ __forceinline__ void mma_tf32(float c[4], const uint32_t a[4], const uint32_t b[2]) {
    asm volatile(
        "mma.sync.aligned.m16n8k8.row.col.f32.tf32.tf32.f32 "
        "{%0,%1,%2,%3}, {%4,%5,%6,%7}, {%8,%9}, {%0,%1,%2,%3};\n"
        : "+f"(c[0]), "+f"(c[1]), "+f"(c[2]), "+f"(c[3])
        : "r"(a[0]), "r"(a[1]), "r"(a[2]), "r"(a[3]), "r"(b[0]), "r"(b[1]));
}

__device__ __forceinline__ void cp_async16(uint32_t smem_addr, const void* gptr) {
    asm volatile("cp.async.cg.shared.global [%0], [%1], 16;\n" :: "r"(smem_addr), "l"(gptr));
}
__device__ __forceinline__ void cp_commit() {
    asm volatile("cp.async.commit_group;\n");
}
template<int N>
__device__ __forceinline__ void cp_wait() {
    asm volatile("cp.async.wait_group %0;\n" :: "n"(N));
}

__device__ __forceinline__ float blockReduceSum256(float v, float* red, int tid) {
    #pragma unroll
    for (int o = 16; o > 0; o >>= 1) v += __shfl_xor_sync(0xffffffffu, v, o);
    if ((tid & 31) == 0) red[tid >> 5] = v;
    __syncthreads();
    if (tid < 8) {
        float r = red[tid];
        #pragma unroll
        for (int o = 4; o > 0; o >>= 1) r += __shfl_xor_sync(0xffu, r, o);
        if (tid == 0) red[32] = r;
    }
    __syncthreads();
    float out = red[32];
    __syncthreads();
    return out;
}

__device__ __forceinline__ float blockReduceMax256(float v, float* red, int tid) {
    #pragma unroll
    for (int o = 16; o > 0; o >>= 1) v = fmaxf(v, __shfl_xor_sync(0xffffffffu, v, o));
    if ((tid & 31) == 0) red[tid >> 5] = v;
    __syncthreads();
    if (tid < 8) {
        float r = red[tid];
        #pragma unroll
        for (int o = 4; o > 0; o >>= 1) r = fmaxf(r, __shfl_xor_sync(0xffu, r, o));
        if (tid == 0) red[32] = r;
    }
    __syncthreads();
    float out = red[32];
    __syncthreads();
    return out;
}

// ---------------- elementwise tf32 rounding ----------------
__global__ void __launch_bounds__(256) round_tf32_kernel(const float* __restrict__ in,
                                                         float* __restrict__ out, int n4) {
    int i = blockIdx.x * 256 + threadIdx.x;
    if (i < n4) {
        float4 v = ((const float4*)in)[i];
        uint4 r;
        r.x = f2tf(v.x); r.y = f2tf(v.y); r.z = f2tf(v.z); r.w = f2tf(v.w);
        ((uint4*)out)[i] = r;
    }
}

// =====================================================================
// Pipelined TF32 GEMM: block 128x128x32, 2-stage cp.async, 8 warps (2x4)
// __launch_bounds__(256,2) caps regs at 128 -> 2 blocks/SM (16 warps).
// =====================================================================
#define APITCH 36
#define BPITCH_NN 136
#define ASZ (128 * APITCH)
#define BSZ_T (128 * APITCH)
#define BSZ_N (32 * BPITCH_NN)
#define STAGES 2

template<int TRANSB, int EPI, int CVT>
__global__ void __launch_bounds__(256, 2) tc_gemm(const float* __restrict__ Ag,
                                                  const float* __restrict__ Bg,
                                                  float* __restrict__ Cg,
                                                  int M, int N, int K,
                                                  long long sA, long long sB, long long sC,
                                                  const float* __restrict__ bias) {
    extern __shared__ float smem[];
    const int BSZ = TRANSB ? BSZ_T : BSZ_N;
    float* AsBase = smem;
    float* BsBase = smem + STAGES * ASZ;

    const float* A = Ag + (long long)blockIdx.z * sA;
    const float* B = Bg + (long long)blockIdx.z * sB;
    float*       C = Cg + (long long)blockIdx.z * sC;
    const int m0 = blockIdx.y * 128, n0 = blockIdx.x * 128;

    const int tid = threadIdx.x;
    const int wid = tid >> 5, lane = tid & 31;
    const int wm = (wid >> 2) * 64;
    const int wn = (wid & 3) * 32;
    const int g = lane >> 2, tg = lane & 3;

    const int nk = K >> 5;

    auto issue_tile = [&](int s, int kt) {
        if (kt < nk) {
            int k0 = kt << 5;
            float* As = AsBase + s * ASZ;
            float* Bs = BsBase + s * BSZ;
            #pragma unroll
            for (int r = 0; r < 4; r++) {
                int c = tid + r * 256;
                int row = c >> 3;
                int kq = (c & 7) << 2;
                int mrow = m0 + row;
                if (mrow >= M) mrow = M - 1;
                uint32_t dst = (uint32_t)__cvta_generic_to_shared(As + row * APITCH + kq);
                cp_async16(dst, A + (long long)mrow * K + k0 + kq);
            }
            if (TRANSB) {
                #pragma unroll
                for (int r = 0; r < 4; r++) {
                    int c = tid + r * 256;
                    int row = c >> 3;
                    int kq = (c & 7) << 2;
                    uint32_t dst = (uint32_t)__cvta_generic_to_shared(Bs + row * APITCH + kq);
                    cp_async16(dst, B + (long long)(n0 + row) * K + k0 + kq);
                }
            } else {
                #pragma unroll
                for (int r = 0; r < 4; r++) {
                    int c = tid + r * 256;
                    int k = c >> 5;
                    int nq = (c & 31) << 2;
                    uint32_t dst = (uint32_t)__cvta_generic_to_shared(Bs + k * BPITCH_NN + nq);
                    cp_async16(dst, B + (long long)(k0 + k) * N + n0 + nq);
                }
            }
        }
        cp_commit();
    };

    auto frag = [&](const float* p) -> uint32_t {
        if (CVT) return f2tf(*p);
        return *(const uint32_t*)p;
    };

    float c[4][4][4];
    #pragma unroll
    for (int mi = 0; mi < 4; mi++)
        #pragma unroll
        for (int ni = 0; ni < 4; ni++)
            #pragma unroll
            for (int r = 0; r < 4; r++) c[mi][ni][r] = 0.f;

    issue_tile(0, 0);

    for (int kt = 0; kt < nk; kt++) {
        issue_tile((kt + 1) % STAGES, kt + 1);
        cp_wait<1>();
        __syncthreads();
        const float* As = AsBase + (kt % STAGES) * ASZ;
        const float* Bs = BsBase + (kt % STAGES) * BSZ;

        #pragma unroll
        for (int kk = 0; kk < 32; kk += 8) {
            uint32_t a[4][4], bfr[4][2];
            #pragma unroll
            for (int mi = 0; mi < 4; mi++) {
                const float* Ar = As + (wm + mi * 16 + g) * APITCH + kk + tg;
                a[mi][0] = frag(Ar);
                a[mi][1] = frag(Ar + 8 * APITCH);
                a[mi][2] = frag(Ar + 4);
                a[mi][3] = frag(Ar + 8 * APITCH + 4);
            }
            if (TRANSB) {
                #pragma unroll
                for (int ni = 0; ni < 4; ni++) {
                    const float* Br = Bs + (wn + ni * 8 + g) * APITCH + kk + tg;
                    bfr[ni][0] = frag(Br);
                    bfr[ni][1] = frag(Br + 4);
                }
            } else {
                #pragma unroll
                for (int ni = 0; ni < 4; ni++) {
                    const float* Br = Bs + (kk + tg) * BPITCH_NN + wn + ni * 8 + g;
                    bfr[ni][0] = frag(Br);
                    bfr[ni][1] = frag(Br + 4 * BPITCH_NN);
                }
            }
            #pragma unroll
            for (int mi = 0; mi < 4; mi++)
                #pragma unroll
                for (int ni = 0; ni < 4; ni++)
                    mma_tf32(c[mi][ni], a[mi], bfr[ni]);
        }
        __syncthreads();
    }

    #pragma unroll
    for (int mi = 0; mi < 4; mi++) {
        int r0 = m0 + wm + mi * 16 + g;
        int r1 = r0 + 8;
        float b0v = 0.f, b1v = 0.f;
        if (EPI) {
            if (r0 < M) b0v = bias[r0];
            if (r1 < M) b1v = bias[r1];
        }
        #pragma unroll
        for (int ni = 0; ni < 4; ni++) {
            int col = n0 + wn + ni * 8 + 2 * tg;
            float v0 = c[mi][ni][0], v1 = c[mi][ni][1];
            float v2 = c[mi][ni][2], v3 = c[mi][ni][3];
            if (EPI) {
                v0 = softplus_f(v0 + b0v); v1 = softplus_f(v1 + b0v);
                v2 = softplus_f(v2 + b1v); v3 = softplus_f(v3 + b1v);
            }
            if (r0 < M) *(float2*)(C + (long long)r0 * N + col) = make_float2(v0, v1);
            if (r1 < M) *(float2*)(C + (long long)r1 * N + col) = make_float2(v2, v3);
        }
    }
}

#define SMEM_T ((STAGES * (ASZ + BSZ_T)) * 4)
#define SMEM_N ((STAGES * (ASZ + BSZ_N)) * 4)

// ---------------- FFT channel-alignment features ----------------
__global__ void __launch_bounds__(32) fft_feat_kernel(const float* __restrict__ xz,
                                                      float* __restrict__ feat) {
    __shared__ float sx[256 * 33];
    __shared__ float twc[16], tws[16];
    int tid = threadIdx.x;
    int bt = blockIdx.y;
    int b = bt >> 3, t = bt & 7;
    int c0 = blockIdx.x * 32;
    if (tid < 16) {
        float ang = tid * 0.39269908169872414f;
        twc[tid] = cosf(ang);
        tws[tid] = sinf(ang);
    }
    const float* xb = xz + ((long long)(b * E2 + c0)) * LSEQ + t * 256;
    for (int i = tid; i < 32 * 256; i += 32) {
        int c = i >> 8, l = i & 255;
        sx[l * 33 + c] = xb[(long long)c * LSEQ + l];
    }
    __syncwarp();
    int c = tid;
    float S_tot = 0.f, S_high = 0.f;
    for (int wq = 0; wq < 9; wq++) {
        float Rr[16], Ri[16];
        #pragma unroll
        for (int h = 0; h < 16; h++) {
            float rr = 0.f, ri = 0.f;
            #pragma unroll
            for (int w = 0; w < 16; w++) {
                float v = sx[(h * 16 + w) * 33 + c];
                int id = (w * wq) & 15;
                rr += v * twc[id];
                ri -= v * tws[id];
            }
            Rr[h] = rr; Ri[h] = ri;
        }
        #pragma unroll
        for (int hq = 0; hq < 16; hq++) {
            float fre = 0.f, fim = 0.f;
            #pragma unroll
            for (int h = 0; h < 16; h++) {
                int id = (h * hq) & 15;
                float cc = twc[id], sn = tws[id];
                fre += Rr[h] * cc + Ri[h] * sn;
                fim += Ri[h] * cc - Rr[h] * sn;
            }
            float mag = sqrtf(fre * fre + fim * fim + 1e-8f);
            S_tot += mag;
            int hs = (hq + 8) & 15;
            int ws = wq + 4; if (ws >= 9) ws -= 9;
            float dh = (hs - 8) * (1.0f / 16.0f);
            float dw = (ws - 4) * (1.0f / 9.0f);
            if (dh * dh + dw * dw >= 0.25f) S_high += mag;
        }
    }
    feat[(long long)bt * DI + c0 + c] = S_high / (S_tot + 1e-8f);
}

// ---------------- alignment loss ----------------
__global__ void __launch_bounds__(256) loss_kernel(const float* __restrict__ feat,
                                                   float* __restrict__ out, long long loss_idx) {
    __shared__ float g[DI];
    __shared__ float red[40];
    int tid = threadIdx.x;
    for (int cc = tid; cc < DI; cc += 256) g[cc] = 0.f;
    __syncthreads();
    for (int i = 0; i < NBT; i++) {
        float ss = 0.f;
        for (int cc = tid; cc < DI; cc += 256) {
            float v = feat[i * DI + cc];
            ss += v * v;
        }
        ss = blockReduceSum256(ss, red, tid);
        float inv = 1.f / fmaxf(sqrtf(ss), 1e-12f);
        for (int cc = tid; cc < DI; cc += 256) g[cc] += feat[i * DI + cc] * inv;
        __syncthreads();
    }
    float tt = 0.f;
    for (int cc = tid; cc < DI; cc += 256) tt += g[cc] * g[cc];
    tt = blockReduceSum256(tt, red, tid);
    if (tid == 0) out[loss_idx] = 1.f - tt / (float)(NBT * NBT);
}

// ---------------- A preparation (invert_A) ----------------
__global__ void __launch_bounds__(256) aprep_kernel(const float* __restrict__ feat,
                                                    const float* __restrict__ A_log,
                                                    float* __restrict__ Aout) {
    __shared__ float sf[DI];
    __shared__ float satt[DI];
    __shared__ float red[40];
    __shared__ float wmx[8][16], wmn[8][16];
    __shared__ float colMx[16], colMn[16];
    int tid = threadIdx.x;
    int lane = tid & 31, wid = tid >> 5;
    for (int cc = tid; cc < DI; cc += 256) {
        float s = 0.f;
        for (int i = 0; i < NBT; i++) s += feat[i * DI + cc];
        sf[cc] = s * (1.0f / NBT);
    }
    __syncthreads();
    float mx = -3.4e38f;
    for (int cc = tid; cc < DI; cc += 256) mx = fmaxf(mx, sf[cc]);
    mx = blockReduceMax256(mx, red, tid);
    float se = 0.f;
    for (int cc = tid; cc < DI; cc += 256) {
        float e = expf(sf[cc] - mx);
        sf[cc] = e;
        se += e;
    }
    se = blockReduceSum256(se, red, tid);
    float inv_se = 1.f / se;
    float cm[16], cn[16];
    #pragma unroll
    for (int n = 0; n < 16; n++) { cm[n] = -3.4e38f; cn[n] = 3.4e38f; }
    float am = 0.f;
    for (int d = tid; d < DI; d += 256) {
        float ss = 0.f;
        #pragma unroll
        for (int n = 0; n < 16; n++) {
            float al = A_log[d * 16 + n];
            float e = expf(al);
            ss += e * e;
            cm[n] = fmaxf(cm[n], al);
            cn[n] = fminf(cn[n], al);
        }
        float an = sqrtf(ss);
        satt[d] = an;
        am = fmaxf(am, an);
    }
    am = blockReduceMax256(am, red, tid);
    #pragma unroll
    for (int o = 16; o > 0; o >>= 1) {
        #pragma unroll
        for (int n = 0; n < 16; n++) {
            cm[n] = fmaxf(cm[n], __shfl_xor_sync(0xffffffffu, cm[n], o));
            cn[n] = fminf(cn[n], __shfl_xor_sync(0xffffffffu, cn[n], o));
        }
    }
    if (lane == 0) {
        #pragma unroll
        for (int n = 0; n < 16; n++) { wmx[wid][n] = cm[n]; wmn[wid][n] = cn[n]; }
    }
    __syncthreads();
    if (tid < 16) {
        float m = -3.4e38f, mn = 3.4e38f;
        for (int w = 0; w < 8; w++) { m = fmaxf(m, wmx[w][tid]); mn = fminf(mn, wmn[w][tid]); }
        colMx[tid] = m; colMn[tid] = mn;
    }
    __syncthreads();
    float inv_am = 1.f / (am + 1e-8f);
    for (int i = tid; i < DI * 16; i += 256) {
        int d = i >> 4, n = i & 15;
        float f = sf[d] * inv_se;
        float att = satt[d] * inv_am;
        float alpha = fminf(fmaxf(f * (1.f - att), 0.f), 1.f);
        float al = A_log[i];
        float fl = colMx[n] + colMn[n] - al;
        float an = (1.f - alpha) * al + alpha * fl;
        Aout[i] = -expf(an);
    }
}

// ---------------- causal depthwise conv (width 4) + silu ----------------
__global__ void __launch_bounds__(256) conv_kernel(const float* __restrict__ xz,
                                                   const float* __restrict__ cw,
                                                   const float* __restrict__ cb,
                                                   float* __restrict__ xc) {
    __shared__ float row[LSEQ + 3];
    int rid = blockIdx.x;
    int b = rid >> 11, d = rid & 2047;
    int tid = threadIdx.x;
    const float* xp = xz + ((long long)b * E2 + d) * LSEQ;
    if (tid < 3) row[tid] = 0.f;
    for (int i = tid; i < LSEQ; i += 256) row[3 + i] = xp[i];
    __syncthreads();
    float w0 = cw[d * 4 + 0], w1 = cw[d * 4 + 1], w2 = cw[d * 4 + 2], w3 = cw[d * 4 + 3];
    float bb = cb[d];
    float* op = xc + ((long long)b * DI + d) * LSEQ;
    for (int i = tid; i < LSEQ; i += 256) {
        float v = bb + w0 * row[i] + w1 * row[i + 1] + w2 * row[i + 2] + w3 * row[i + 3];
        op[i] = v / (1.f + expf(-v));
    }
}

// ---------------- selective scan (y written tf32-rounded) ----------------
__global__ void __launch_bounds__(256) scan_kernel(const float* __restrict__ delta,
                                                   const float* __restrict__ xc,
                                                   const float* __restrict__ xz,
                                                   const float* __restrict__ xdbl,
                                                   const float* __restrict__ A,
                                                   const float* __restrict__ Dp,
                                                   float* __restrict__ y) {
    __shared__ float sDel[64][17], sU[64][17], sZ[64][17];
    __shared__ float sB[64][17], sC[64][17], sY[64][17];
    int tid = threadIdx.x;
    int ci = tid >> 4, n = tid & 15;
    int b = blockIdx.y;
    int d0 = blockIdx.x * 16;
    int d = d0 + ci;
    const float* delp = delta + ((long long)b * DI + d0) * LSEQ;
    const float* up   = xc    + ((long long)b * DI + d0) * LSEQ;
    const float* zp   = xz    + ((long long)b * E2 + DI + d0) * LSEQ;
    const float* bp   = xdbl  + ((long long)b * 96 + 64) * LSEQ;
    const float* cp   = xdbl  + ((long long)b * 96 + 80) * LSEQ;
    float*       yp   = y     + (long long)b * LSEQ * DI;
    float a = A[d * 16 + n];
    float dD = Dp[d];
    float s = 0.f;
    for (int l0 = 0; l0 < LSEQ; l0 += 64) {
        for (int i = tid; i < 1024; i += 256) {
            int cc = i >> 6, j = i & 63;
            sDel[j][cc] = delp[(long long)cc * LSEQ + l0 + j];
            sU[j][cc]   = up[(long long)cc * LSEQ + l0 + j];
            sZ[j][cc]   = zp[(long long)cc * LSEQ + l0 + j];
            sB[j][cc]   = bp[(long long)cc * LSEQ + l0 + j];
            sC[j][cc]   = cp[(long long)cc * LSEQ + l0 + j];
        }
        __syncthreads();
        #pragma unroll 4
        for (int j = 0; j < 64; j++) {
            float dl = sDel[j][ci];
            float u  = sU[j][ci];
            float bb = sB[j][n];
            float ccv = sC[j][n];
            s = s * __expf(dl * a) + (dl * u) * bb;
            float p = s * ccv;
            #pragma unroll
            for (int o = 8; o > 0; o >>= 1) p += __shfl_xor_sync(0xffffffffu, p, o, 16);
            if (n == 0) {
                float z = sZ[j][ci];
                float yy = (p + u * dD) * (z / (1.f + __expf(-z)));
                sY[j][ci] = __uint_as_float(f2tf(yy));
            }
        }
        __syncthreads();
        for (int i = tid; i < 1024; i += 256) {
            int j = i >> 4, cc = i & 15;
            yp[(long long)(l0 + j) * DI + d0 + cc] = sY[j][cc];
        }
        __syncthreads();
    }
}

// ---------------- launch ----------------
extern "C" void kernel_launch(void* const* d_in, const int* in_sizes, int n_in,
                              void* d_out, int out_size) {
    const float* hidden    = (const float*)d_in[0];
    const float* in_proj_w = (const float*)d_in[4];
    const float* conv_w    = (const float*)d_in[5];
    const float* conv_b    = (const float*)d_in[6];
    const float* x_proj_w  = (const float*)d_in[7];
    const float* dt_proj_w = (const float*)d_in[8];
    const float* dt_proj_b = (const float*)d_in[9];
    const float* A_log     = (const float*)d_in[10];
    const float* Dparam    = (const float*)d_in[11];
    const float* out_proj_w= (const float*)d_in[12];
    float* out = (float*)d_out;

    float *xzp, *xcp, *xdblp, *deltap, *yp, *featp, *Ap, *hp, *w1p, *wop;
    cudaGetSymbolAddress((void**)&xzp, g_xz);
    cudaGetSymbolAddress((void**)&xcp, g_xc);
    cudaGetSymbolAddress((void**)&xdblp, g_xdbl);
    cudaGetSymbolAddress((void**)&deltap, g_delta);
    cudaGetSymbolAddress((void**)&yp, g_y);
    cudaGetSymbolAddress((void**)&featp, g_feat);
    cudaGetSymbolAddress((void**)&Ap, g_A);
    cudaGetSymbolAddress((void**)&hp, g_h);
    cudaGetSymbolAddress((void**)&w1p, g_w1);
    cudaGetSymbolAddress((void**)&wop, g_wo);

    cudaFuncSetAttribute(tc_gemm<1, 0, 0>, cudaFuncAttributeMaxDynamicSharedMemorySize, SMEM_T);
    cudaFuncSetAttribute(tc_gemm<0, 0, 1>, cudaFuncAttributeMaxDynamicSharedMemorySize, SMEM_N);
    cudaFuncSetAttribute(tc_gemm<0, 1, 1>, cudaFuncAttributeMaxDynamicSharedMemorySize, SMEM_N);

    // 0) pre-round GEMM operands to tf32
    round_tf32_kernel<<<(8388608 / 4 + 255) / 256, 256>>>(hidden, hp, 8388608 / 4);
    round_tf32_kernel<<<(4194304 / 4 + 255) / 256, 256>>>(in_proj_w, w1p, 4194304 / 4);
    round_tf32_kernel<<<(2097152 / 4 + 255) / 256, 256>>>(out_proj_w, wop, 2097152 / 4);

    // 1) xz = in_proj
    {
        dim3 grid(LSEQ / 128, E2 / 128, 4);
        tc_gemm<1, 0, 0><<<grid, 256, SMEM_T>>>(w1p, hp, xzp, E2, LSEQ, DM,
                                                0LL, (long long)LSEQ * DM, (long long)E2 * LSEQ,
                                                (const float*)0);
    }
    // 2) FFT features
    {
        dim3 grid(DI / 32, 32);
        fft_feat_kernel<<<grid, 32>>>(xzp, featp);
    }
    // 3) loss -> out[last]
    loss_kernel<<<1, 256>>>(featp, out, (long long)out_size - 1);
    // 4) A prep
    aprep_kernel<<<1, 256>>>(featp, A_log, Ap);
    // 5) conv + silu
    conv_kernel<<<4 * DI, 256>>>(xzp, conv_w, conv_b, xcp);
    // 6) x_dbl
    {
        dim3 grid(LSEQ / 128, 1, 4);
        tc_gemm<0, 0, 1><<<grid, 256, SMEM_N>>>(x_proj_w, xcp, xdblp, 96, LSEQ, DI,
                                                0LL, (long long)DI * LSEQ, (long long)96 * LSEQ,
                                                (const float*)0);
    }
    // 7) delta
    {
        dim3 grid(LSEQ / 128, DI / 128, 4);
        tc_gemm<0, 1, 1><<<grid, 256, SMEM_N>>>(dt_proj_w, xdblp, deltap, DI, LSEQ, 64,
                                                0LL, (long long)96 * LSEQ, (long long)DI * LSEQ,
                                                dt_proj_b);
    }
    // 8) scan -> y
    {
        dim3 grid(DI / 16, 4);
        scan_kernel<<<grid, 256>>>(deltap, xcp, xzp, xdblp, Ap, Dparam, yp);
    }
    // 9) out = y @ out_proj^T
    {
        dim3 grid(DM / 128, LSEQ / 128, 4);
        tc_gemm<1, 0, 0><<<grid, 256, SMEM_T>>>(yp, wop, out, LSEQ, DM, DI,
                                                (long long)LSEQ * DI, 0LL, (long long)LSEQ * DM,
                                                (const float*)0);
    }
}

// round 9
// speedup vs baseline: 2.1279x; 1.0193x over previous
#include <cuda_runtime.h>
#include <cuda_bf16.h>
#include <math.h>
#include <stdint.h>

#define LSEQ 2048
#define DI   2048
#define DM   1024
#define E2   4096
#define NST  16
#define NBT  32

// ---------------- scratch ----------------
__device__ float g_xz[33554432];    // [4][4096][2048]
__device__ float g_xc[16777216];    // [4][2048][2048]
__device__ float g_xdbl[786432];    // [4][96][2048]
__device__ float g_delta[16777216]; // [4][2048][2048]
__device__ float g_y[16777216];     // [4][2048][2048] (l,d)
__device__ float g_feat[65536];     // [32][2048]
__device__ float g_A[32768];        // [2048][16]
__device__ float g_h[8388608];      // tf32-rounded hidden
__device__ float g_w1[4194304];     // tf32-rounded in_proj_w
__device__ float g_wo[2097152];     // tf32-rounded out_proj_w

__device__ __forceinline__ float softplus_f(float x) {
    return fmaxf(x, 0.f) + log1pf(expf(-fabsf(x)));
}

__device__ __forceinline__ uint32_t f2tf(float f) {
    uint32_t r;
    asm("cvt.rna.tf32.f32 %0, %1;" : "=r"(r) : "f"(f));
    return r;
}

__device__ __forceinline__ void mma_tf32(float c[4], const uint32_t a[4], const uint32_t b[2]) {
    asm volatile(
        "mma.sync.aligned.m16n8k8.row.col.f32.tf32.tf32.f32 "
        "{%0,%1,%2,%3}, {%4,%5,%6,%7}, {%8,%9}, {%0,%1,%2,%3};\n"
        : "+f"(c[0]), "+f"(c[1]), "+f"(c[2]), "+f"(c[3])
        : "r"(a[0]), "r"(a[1]), "r"(a[2]), "r"(a[3]), "r"(b[0]), "r"(b[1]));
}

__device__ __forceinline__ void ldm_x4(uint32_t r[4], uint32_t addr) {
    asm volatile("ldmatrix.sync.aligned.m8n8.x4.shared.b16 {%0,%1,%2,%3}, [%4];"
        : "=r"(r[0]), "=r"(r[1]), "=r"(r[2]), "=r"(r[3]) : "r"(addr));
}

__device__ __forceinline__ void cp_async16(uint32_t smem_addr, const void* gptr) {
    asm volatile("cp.async.cg.shared.global [%0], [%1], 16;\n" :: "r"(smem_addr), "l"(gptr));
}
__device__ __forceinline__ void cp_commit() {
    asm volatile("cp.async.commit_group;\n");
}
template<int N>
__device__ __forceinline__ void cp_wait() {
    asm volatile("cp.async.wait_group %0;\n" :: "n"(N));
}

__device__ __forceinline__ float blockReduceSum256(float v, float* red, int tid) {
    #pragma unroll
    for (int o = 16; o > 0; o >>= 1) v += __shfl_xor_sync(0xffffffffu, v, o);
    if ((tid & 31) == 0) red[tid >> 5] = v;
    __syncthreads();
    if (tid < 8) {
        float r = red[tid];
        #pragma unroll
        for (int o = 4; o > 0; o >>= 1) r += __shfl_xor_sync(0xffu, r, o);
        if (tid == 0) red[32] = r;
    }
    __syncthreads();
    float out = red[32];
    __syncthreads();
    return out;
}

__device__ __forceinline__ float blockReduceMax256(float v, float* red, int tid) {
    #pragma unroll
    for (int o = 16; o > 0; o >>= 1) v = fmaxf(v, __shfl_xor_sync(0xffffffffu, v, o));
    if ((tid & 31) == 0) red[tid >> 5] = v;
    __syncthreads();
    if (tid < 8) {
        float r = red[tid];
        #pragma unroll
        for (int o = 4; o > 0; o >>= 1) r = fmaxf(r, __shfl_xor_sync(0xffu, r, o));
        if (tid == 0) red[32] = r;
    }
    __syncthreads();
    float out = red[32];
    __syncthreads();
    return out;
}

// ---------------- elementwise tf32 rounding ----------------
__global__ void __launch_bounds__(256) round_tf32_kernel(const float* __restrict__ in,
                                                         float* __restrict__ out, int n4) {
    int i = blockIdx.x * 256 + threadIdx.x;
    if (i < n4) {
        float4 v = ((const float4*)in)[i];
        uint4 r;
        r.x = f2tf(v.x); r.y = f2tf(v.y); r.z = f2tf(v.z); r.w = f2tf(v.w);
        ((uint4*)out)[i] = r;
    }
}

// =====================================================================
// Pipelined TF32 GEMM: block 128x128x32, 2-stage cp.async, 8 warps (2x4)
// TRANSB=1 path uses ldmatrix (LDSM) fragment loads: 6 LDSM per k-slice.
// =====================================================================
#define APITCH 36
#define BPITCH_NN 136
#define ASZ (128 * APITCH)
#define BSZ_T (128 * APITCH)
#define BSZ_N (32 * BPITCH_NN)
#define STAGES 2

template<int TRANSB, int EPI, int CVT>
__global__ void __launch_bounds__(256, 2) tc_gemm(const float* __restrict__ Ag,
                                                  const float* __restrict__ Bg,
                                                  float* __restrict__ Cg,
                                                  int M, int N, int K,
                                                  long long sA, long long sB, long long sC,
                                                  const float* __restrict__ bias) {
    extern __shared__ float smem[];
    const int BSZ = TRANSB ? BSZ_T : BSZ_N;
    float* AsBase = smem;
    float* BsBase = smem + STAGES * ASZ;

    const float* A = Ag + (long long)blockIdx.z * sA;
    const float* B = Bg + (long long)blockIdx.z * sB;
    float*       C = Cg + (long long)blockIdx.z * sC;
    const int m0 = blockIdx.y * 128, n0 = blockIdx.x * 128;

    const int tid = threadIdx.x;
    const int wid = tid >> 5, lane = tid & 31;
    const int wm = (wid >> 2) * 64;
    const int wn = (wid & 3) * 32;
    const int g = lane >> 2, tg = lane & 3;
    const int r8 = lane & 7, q = lane >> 3;   // ldmatrix lane decomposition

    const int nk = K >> 5;

    auto issue_tile = [&](int s, int kt) {
        if (kt < nk) {
            int k0 = kt << 5;
            float* As = AsBase + s * ASZ;
            float* Bs = BsBase + s * BSZ;
            #pragma unroll
            for (int r = 0; r < 4; r++) {
                int c = tid + r * 256;
                int row = c >> 3;
                int kq = (c & 7) << 2;
                int mrow = m0 + row;
                if (mrow >= M) mrow = M - 1;
                uint32_t dst = (uint32_t)__cvta_generic_to_shared(As + row * APITCH + kq);
                cp_async16(dst, A + (long long)mrow * K + k0 + kq);
            }
            if (TRANSB) {
                #pragma unroll
                for (int r = 0; r < 4; r++) {
                    int c = tid + r * 256;
                    int row = c >> 3;
                    int kq = (c & 7) << 2;
                    uint32_t dst = (uint32_t)__cvta_generic_to_shared(Bs + row * APITCH + kq);
                    cp_async16(dst, B + (long long)(n0 + row) * K + k0 + kq);
                }
            } else {
                #pragma unroll
                for (int r = 0; r < 4; r++) {
                    int c = tid + r * 256;
                    int k = c >> 5;
                    int nq = (c & 31) << 2;
                    uint32_t dst = (uint32_t)__cvta_generic_to_shared(Bs + k * BPITCH_NN + nq);
                    cp_async16(dst, B + (long long)(k0 + k) * N + n0 + nq);
                }
            }
        }
        cp_commit();
    };

    auto frag = [&](const float* p) -> uint32_t {
        if (CVT) return f2tf(*p);
        return *(const uint32_t*)p;
    };

    float c[4][4][4];
    #pragma unroll
    for (int mi = 0; mi < 4; mi++)
        #pragma unroll
        for (int ni = 0; ni < 4; ni++)
            #pragma unroll
            for (int r = 0; r < 4; r++) c[mi][ni][r] = 0.f;

    issue_tile(0, 0);

    for (int kt = 0; kt < nk; kt++) {
        issue_tile((kt + 1) % STAGES, kt + 1);
        cp_wait<1>();
        __syncthreads();
        const float* As = AsBase + (kt % STAGES) * ASZ;
        const float* Bs = BsBase + (kt % STAGES) * BSZ;

        #pragma unroll
        for (int kk = 0; kk < 32; kk += 8) {
            uint32_t a[4][4], bfr[4][2];
            if (TRANSB) {
                // ldmatrix A: one x4 per mi tile (rows {+0,+8} x cols {kk,kk+4})
                #pragma unroll
                for (int mi = 0; mi < 4; mi++) {
                    const float* ap = As + (wm + mi * 16 + ((q & 1) << 3) + r8) * APITCH
                                         + kk + ((q >> 1) << 2);
                    ldm_x4(a[mi], (uint32_t)__cvta_generic_to_shared(ap));
                }
                // ldmatrix B: one x4 covers two 8-wide n tiles
                #pragma unroll
                for (int nn = 0; nn < 2; nn++) {
                    uint32_t bt[4];
                    const float* bp = Bs + (wn + nn * 16 + ((q & 2) << 2) + r8) * APITCH
                                         + kk + ((q & 1) << 2);
                    ldm_x4(bt, (uint32_t)__cvta_generic_to_shared(bp));
                    bfr[2 * nn][0] = bt[0];     bfr[2 * nn][1] = bt[1];
                    bfr[2 * nn + 1][0] = bt[2]; bfr[2 * nn + 1][1] = bt[3];
                }
            } else {
                #pragma unroll
                for (int mi = 0; mi < 4; mi++) {
                    const float* Ar = As + (wm + mi * 16 + g) * APITCH + kk + tg;
                    a[mi][0] = frag(Ar);
                    a[mi][1] = frag(Ar + 8 * APITCH);
                    a[mi][2] = frag(Ar + 4);
                    a[mi][3] = frag(Ar + 8 * APITCH + 4);
                }
                #pragma unroll
                for (int ni = 0; ni < 4; ni++) {
                    const float* Br = Bs + (kk + tg) * BPITCH_NN + wn + ni * 8 + g;
                    bfr[ni][0] = frag(Br);
                    bfr[ni][1] = frag(Br + 4 * BPITCH_NN);
                }
            }
            #pragma unroll
            for (int mi = 0; mi < 4; mi++)
                #pragma unroll
                for (int ni = 0; ni < 4; ni++)
                    mma_tf32(c[mi][ni], a[mi], bfr[ni]);
        }
        __syncthreads();
    }

    #pragma unroll
    for (int mi = 0; mi < 4; mi++) {
        int r0 = m0 + wm + mi * 16 + g;
        int r1 = r0 + 8;
        float b0v = 0.f, b1v = 0.f;
        if (EPI) {
            if (r0 < M) b0v = bias[r0];
            if (r1 < M) b1v = bias[r1];
        }
        #pragma unroll
        for (int ni = 0; ni < 4; ni++) {
            int col = n0 + wn + ni * 8 + 2 * tg;
            float v0 = c[mi][ni][0], v1 = c[mi][ni][1];
            float v2 = c[mi][ni][2], v3 = c[mi][ni][3];
            if (EPI) {
                v0 = softplus_f(v0 + b0v); v1 = softplus_f(v1 + b0v);
                v2 = softplus_f(v2 + b1v); v3 = softplus_f(v3 + b1v);
            }
            if (r0 < M) *(float2*)(C + (long long)r0 * N + col) = make_float2(v0, v1);
            if (r1 < M) *(float2*)(C + (long long)r1 * N + col) = make_float2(v2, v3);
        }
    }
}

#define SMEM_T ((STAGES * (ASZ + BSZ_T)) * 4)
#define SMEM_N ((STAGES * (ASZ + BSZ_N)) * 4)

// ---------------- FFT channel-alignment features ----------------
__global__ void __launch_bounds__(32) fft_feat_kernel(const float* __restrict__ xz,
                                                      float* __restrict__ feat) {
    __shared__ float sx[256 * 33];
    __shared__ float twc[16], tws[16];
    int tid = threadIdx.x;
    int bt = blockIdx.y;
    int b = bt >> 3, t = bt & 7;
    int c0 = blockIdx.x * 32;
    if (tid < 16) {
        float ang = tid * 0.39269908169872414f;
        twc[tid] = cosf(ang);
        tws[tid] = sinf(ang);
    }
    const float* xb = xz + ((long long)(b * E2 + c0)) * LSEQ + t * 256;
    for (int i = tid; i < 32 * 256; i += 32) {
        int c = i >> 8, l = i & 255;
        sx[l * 33 + c] = xb[(long long)c * LSEQ + l];
    }
    __syncwarp();
    int c = tid;
    float S_tot = 0.f, S_high = 0.f;
    for (int wq = 0; wq < 9; wq++) {
        float Rr[16], Ri[16];
        #pragma unroll
        for (int h = 0; h < 16; h++) {
            float rr = 0.f, ri = 0.f;
            #pragma unroll
            for (int w = 0; w < 16; w++) {
                float v = sx[(h * 16 + w) * 33 + c];
                int id = (w * wq) & 15;
                rr += v * twc[id];
                ri -= v * tws[id];
            }
            Rr[h] = rr; Ri[h] = ri;
        }
        #pragma unroll
        for (int hq = 0; hq < 16; hq++) {
            float fre = 0.f, fim = 0.f;
            #pragma unroll
            for (int h = 0; h < 16; h++) {
                int id = (h * hq) & 15;
                float cc = twc[id], sn = tws[id];
                fre += Rr[h] * cc + Ri[h] * sn;
                fim += Ri[h] * cc - Rr[h] * sn;
            }
            float mag = sqrtf(fre * fre + fim * fim + 1e-8f);
            S_tot += mag;
            int hs = (hq + 8) & 15;
            int ws = wq + 4; if (ws >= 9) ws -= 9;
            float dh = (hs - 8) * (1.0f / 16.0f);
            float dw = (ws - 4) * (1.0f / 9.0f);
            if (dh * dh + dw * dw >= 0.25f) S_high += mag;
        }
    }
    feat[(long long)bt * DI + c0 + c] = S_high / (S_tot + 1e-8f);
}

// ---------------- alignment loss ----------------
__global__ void __launch_bounds__(256) loss_kernel(const float* __restrict__ feat,
                                                   float* __restrict__ out, long long loss_idx) {
    __shared__ float g[DI];
    __shared__ float red[40];
    int tid = threadIdx.x;
    for (int cc = tid; cc < DI; cc += 256) g[cc] = 0.f;
    __syncthreads();
    for (int i = 0; i < NBT; i++) {
        float ss = 0.f;
        for (int cc = tid; cc < DI; cc += 256) {
            float v = feat[i * DI + cc];
            ss += v * v;
        }
        ss = blockReduceSum256(ss, red, tid);
        float inv = 1.f / fmaxf(sqrtf(ss), 1e-12f);
        for (int cc = tid; cc < DI; cc += 256) g[cc] += feat[i * DI + cc] * inv;
        __syncthreads();
    }
    float tt = 0.f;
    for (int cc = tid; cc < DI; cc += 256) tt += g[cc] * g[cc];
    tt = blockReduceSum256(tt, red, tid);
    if (tid == 0) out[loss_idx] = 1.f - tt / (float)(NBT * NBT);
}

// ---------------- A preparation (invert_A) ----------------
__global__ void __launch_bounds__(256) aprep_kernel(const float* __restrict__ feat,
                                                    const float* __restrict__ A_log,
                                                    float* __restrict__ Aout) {
    __shared__ float sf[DI];
    __shared__ float satt[DI];
    __shared__ float red[40];
    __shared__ float wmx[8][16], wmn[8][16];
    __shared__ float colMx[16], colMn[16];
    int tid = threadIdx.x;
    int lane = tid & 31, wid = tid >> 5;
    for (int cc = tid; cc < DI; cc += 256) {
        float s = 0.f;
        for (int i = 0; i < NBT; i++) s += feat[i * DI + cc];
        sf[cc] = s * (1.0f / NBT);
    }
    __syncthreads();
    float mx = -3.4e38f;
    for (int cc = tid; cc < DI; cc += 256) mx = fmaxf(mx, sf[cc]);
    mx = blockReduceMax256(mx, red, tid);
    float se = 0.f;
    for (int cc = tid; cc < DI; cc += 256) {
        float e = expf(sf[cc] - mx);
        sf[cc] = e;
        se += e;
    }
    se = blockReduceSum256(se, red, tid);
    float inv_se = 1.f / se;
    float cm[16], cn[16];
    #pragma unroll
    for (int n = 0; n < 16; n++) { cm[n] = -3.4e38f; cn[n] = 3.4e38f; }
    float am = 0.f;
    for (int d = tid; d < DI; d += 256) {
        float ss = 0.f;
        #pragma unroll
        for (int n = 0; n < 16; n++) {
            float al = A_log[d * 16 + n];
            float e = expf(al);
            ss += e * e;
            cm[n] = fmaxf(cm[n], al);
            cn[n] = fminf(cn[n], al);
        }
        float an = sqrtf(ss);
        satt[d] = an;
        am = fmaxf(am, an);
    }
    am = blockReduceMax256(am, red, tid);
    #pragma unroll
    for (int o = 16; o > 0; o >>= 1) {
        #pragma unroll
        for (int n = 0; n < 16; n++) {
            cm[n] = fmaxf(cm[n], __shfl_xor_sync(0xffffffffu, cm[n], o));
            cn[n] = fminf(cn[n], __shfl_xor_sync(0xffffffffu, cn[n], o));
        }
    }
    if (lane == 0) {
        #pragma unroll
        for (int n = 0; n < 16; n++) { wmx[wid][n] = cm[n]; wmn[wid][n] = cn[n]; }
    }
    __syncthreads();
    if (tid < 16) {
        float m = -3.4e38f, mn = 3.4e38f;
        for (int w = 0; w < 8; w++) { m = fmaxf(m, wmx[w][tid]); mn = fminf(mn, wmn[w][tid]); }
        colMx[tid] = m; colMn[tid] = mn;
    }
    __syncthreads();
    float inv_am = 1.f / (am + 1e-8f);
    for (int i = tid; i < DI * 16; i += 256) {
        int d = i >> 4, n = i & 15;
        float f = sf[d] * inv_se;
        float att = satt[d] * inv_am;
        float alpha = fminf(fmaxf(f * (1.f - att), 0.f), 1.f);
        float al = A_log[i];
        float fl = colMx[n] + colMn[n] - al;
        float an = (1.f - alpha) * al + alpha * fl;
        Aout[i] = -expf(an);
    }
}

// ---------------- causal depthwise conv (width 4) + silu ----------------
__global__ void __launch_bounds__(256) conv_kernel(const float* __restrict__ xz,
                                                   const float* __restrict__ cw,
                                                   const float* __restrict__ cb,
                                                   float* __restrict__ xc) {
    __shared__ float row[LSEQ + 3];
    int rid = blockIdx.x;
    int b = rid >> 11, d = rid & 2047;
    int tid = threadIdx.x;
    const float* xp = xz + ((long long)b * E2 + d) * LSEQ;
    if (tid < 3) row[tid] = 0.f;
    for (int i = tid; i < LSEQ; i += 256) row[3 + i] = xp[i];
    __syncthreads();
    float w0 = cw[d * 4 + 0], w1 = cw[d * 4 + 1], w2 = cw[d * 4 + 2], w3 = cw[d * 4 + 3];
    float bb = cb[d];
    float* op = xc + ((long long)b * DI + d) * LSEQ;
    for (int i = tid; i < LSEQ; i += 256) {
        float v = bb + w0 * row[i] + w1 * row[i + 1] + w2 * row[i + 2] + w3 * row[i + 3];
        op[i] = v / (1.f + expf(-v));
    }
}

// ---------------- selective scan (y written tf32-rounded) ----------------
__global__ void __launch_bounds__(256) scan_kernel(const float* __restrict__ delta,
                                                   const float* __restrict__ xc,
                                                   const float* __restrict__ xz,
                                                   const float* __restrict__ xdbl,
                                                   const float* __restrict__ A,
                                                   const float* __restrict__ Dp,
                                                   float* __restrict__ y) {
    __shared__ float sDel[64][17], sU[64][17], sZ[64][17];
    __shared__ float sB[64][17], sC[64][17], sY[64][17];
    int tid = threadIdx.x;
    int ci = tid >> 4, n = tid & 15;
    int b = blockIdx.y;
    int d0 = blockIdx.x * 16;
    int d = d0 + ci;
    const float* delp = delta + ((long long)b * DI + d0) * LSEQ;
    const float* up   = xc    + ((long long)b * DI + d0) * LSEQ;
    const float* zp   = xz    + ((long long)b * E2 + DI + d0) * LSEQ;
    const float* bp   = xdbl  + ((long long)b * 96 + 64) * LSEQ;
    const float* cp   = xdbl  + ((long long)b * 96 + 80) * LSEQ;
    float*       yp   = y     + (long long)b * LSEQ * DI;
    float a = A[d * 16 + n];
    float dD = Dp[d];
    float s = 0.f;
    for (int l0 = 0; l0 < LSEQ; l0 += 64) {
        for (int i = tid; i < 1024; i += 256) {
            int cc = i >> 6, j = i & 63;
            sDel[j][cc] = delp[(long long)cc * LSEQ + l0 + j];
            sU[j][cc]   = up[(long long)cc * LSEQ + l0 + j];
            sZ[j][cc]   = zp[(long long)cc * LSEQ + l0 + j];
            sB[j][cc]   = bp[(long long)cc * LSEQ + l0 + j];
            sC[j][cc]   = cp[(long long)cc * LSEQ + l0 + j];
        }
        __syncthreads();
        #pragma unroll 4
        for (int j = 0; j < 64; j++) {
            float dl = sDel[j][ci];
            float u  = sU[j][ci];
            float bb = sB[j][n];
            float ccv = sC[j][n];
            s = s * __expf(dl * a) + (dl * u) * bb;
            float p = s * ccv;
            #pragma unroll
            for (int o = 8; o > 0; o >>= 1) p += __shfl_xor_sync(0xffffffffu, p, o, 16);
            if (n == 0) {
                float z = sZ[j][ci];
                float yy = (p + u * dD) * (z / (1.f + __expf(-z)));
                sY[j][ci] = __uint_as_float(f2tf(yy));
            }
        }
        __syncthreads();
        for (int i = tid; i < 1024; i += 256) {
            int j = i >> 4, cc = i & 15;
            yp[(long long)(l0 + j) * DI + d0 + cc] = sY[j][cc];
        }
        __syncthreads();
    }
}

// ---------------- launch ----------------
extern "C" void kernel_launch(void* const* d_in, const int* in_sizes, int n_in,
                              void* d_out, int out_size) {
    const float* hidden    = (const float*)d_in[0];
    const float* in_proj_w = (const float*)d_in[4];
    const float* conv_w    = (const float*)d_in[5];
    const float* conv_b    = (const float*)d_in[6];
    const float* x_proj_w  = (const float*)d_in[7];
    const float* dt_proj_w = (const float*)d_in[8];
    const float* dt_proj_b = (const float*)d_in[9];
    const float* A_log     = (const float*)d_in[10];
    const float* Dparam    = (const float*)d_in[11];
    const float* out_proj_w= (const float*)d_in[12];
    float* out = (float*)d_out;

    float *xzp, *xcp, *xdblp, *deltap, *yp, *featp, *Ap, *hp, *w1p, *wop;
    cudaGetSymbolAddress((void**)&xzp, g_xz);
    cudaGetSymbolAddress((void**)&xcp, g_xc);
    cudaGetSymbolAddress((void**)&xdblp, g_xdbl);
    cudaGetSymbolAddress((void**)&deltap, g_delta);
    cudaGetSymbolAddress((void**)&yp, g_y);
    cudaGetSymbolAddress((void**)&featp, g_feat);
    cudaGetSymbolAddress((void**)&Ap, g_A);
    cudaGetSymbolAddress((void**)&hp, g_h);
    cudaGetSymbolAddress((void**)&w1p, g_w1);
    cudaGetSymbolAddress((void**)&wop, g_wo);

    cudaFuncSetAttribute(tc_gemm<1, 0, 0>, cudaFuncAttributeMaxDynamicSharedMemorySize, SMEM_T);
    cudaFuncSetAttribute(tc_gemm<0, 0, 1>, cudaFuncAttributeMaxDynamicSharedMemorySize, SMEM_N);
    cudaFuncSetAttribute(tc_gemm<0, 1, 1>, cudaFuncAttributeMaxDynamicSharedMemorySize, SMEM_N);

    // 0) pre-round GEMM operands to tf32
    round_tf32_kernel<<<(8388608 / 4 + 255) / 256, 256>>>(hidden, hp, 8388608 / 4);
    round_tf32_kernel<<<(4194304 / 4 + 255) / 256, 256>>>(in_proj_w, w1p, 4194304 / 4);
    round_tf32_kernel<<<(2097152 / 4 + 255) / 256, 256>>>(out_proj_w, wop, 2097152 / 4);

    // 1) xz = in_proj
    {
        dim3 grid(LSEQ / 128, E2 / 128, 4);
        tc_gemm<1, 0, 0><<<grid, 256, SMEM_T>>>(w1p, hp, xzp, E2, LSEQ, DM,
                                                0LL, (long long)LSEQ * DM, (long long)E2 * LSEQ,
                                                (const float*)0);
    }
    // 2) FFT features
    {
        dim3 grid(DI / 32, 32);
        fft_feat_kernel<<<grid, 32>>>(xzp, featp);
    }
    // 3) loss -> out[last]
    loss_kernel<<<1, 256>>>(featp, out, (long long)out_size - 1);
    // 4) A prep
    aprep_kernel<<<1, 256>>>(featp, A_log, Ap);
    // 5) conv + silu
    conv_kernel<<<4 * DI, 256>>>(xzp, conv_w, conv_b, xcp);
    // 6) x_dbl
    {
        dim3 grid(LSEQ / 128, 1, 4);
        tc_gemm<0, 0, 1><<<grid, 256, SMEM_N>>>(x_proj_w, xcp, xdblp, 96, LSEQ, DI,
                                                0LL, (long long)DI * LSEQ, (long long)96 * LSEQ,
                                                (const float*)0);
    }
    // 7) delta
    {
        dim3 grid(LSEQ / 128, DI / 128, 4);
        tc_gemm<0, 1, 1><<<grid, 256, SMEM_N>>>(dt_proj_w, xdblp, deltap, DI, LSEQ, 64,
                                                0LL, (long long)96 * LSEQ, (long long)DI * LSEQ,
                                                dt_proj_b);
    }
    // 8) scan -> y
    {
        dim3 grid(DI / 16, 4);
        scan_kernel<<<grid, 256>>>(deltap, xcp, xzp, xdblp, Ap, Dparam, yp);
    }
    // 9) out = y @ out_proj^T
    {
        dim3 grid(DM / 128, LSEQ / 128, 4);
        tc_gemm<1, 0, 0><<<grid, 256, SMEM_T>>>(yp, wop, out, LSEQ, DM, DI,
                                                (long long)LSEQ * DI, 0LL, (long long)LSEQ * DM,
                                                (const float*)0);
    }
}